// round 9
// baseline (speedup 1.0000x reference)
#include <cuda_runtime.h>
#include <cstdint>
#include <cstddef>

#define MAXN 131072

// scratch (device globals: no allocation allowed)
__device__ float g_q[MAXN * 64];
__device__ float g_k[MAXN * 64];
__device__ float g_v[MAXN * 64];
__device__ float4 g_p4[MAXN];

// ---- packed fp32x2 ops (sm_103a FFMA2 path) ----
__device__ __forceinline__ float2 fma2(float2 a, float2 b, float2 c) {
    float2 d;
    asm("fma.rn.f32x2 %0, %1, %2, %3;"
        : "=l"(*(unsigned long long*)&d)
        : "l"(*(unsigned long long*)&a),
          "l"(*(unsigned long long*)&b),
          "l"(*(unsigned long long*)&c));
    return d;
}
__device__ __forceinline__ float2 add2(float2 a, float2 b) {
    float2 d;
    asm("add.rn.f32x2 %0, %1, %2;"
        : "=l"(*(unsigned long long*)&d)
        : "l"(*(unsigned long long*)&a),
          "l"(*(unsigned long long*)&b));
    return d;
}

// ============================================================================
// Kernel 1: fused q/k/v = x @ [Wq|Wk|Wv] + b, plus p -> g_p4 repack.
// 128-row tile; thread = 8 rows x (3 matrices x 4 cols).
// Per k-iter: 48 fma2 vs 11 LDS (8 scalar x = 2-addr broadcast,
// 3 conflict-free LDS.128 w) -> ~81% fma issue fraction.
// ============================================================================
__global__ __launch_bounds__(256) void qkv_kernel(
    const float* __restrict__ x, const float* __restrict__ p,
    const float* __restrict__ Wq, const float* __restrict__ bq,
    const float* __restrict__ Wk, const float* __restrict__ bk,
    const float* __restrict__ Wv, const float* __restrict__ bv,
    int N)
{
    extern __shared__ float smem[];
    float* xs = smem;                  // 128*65 = 8320 floats (stride 65)
    float* ws = smem + 8320;           // 64*192 = 12288 floats
    const int tid = threadIdx.x;
    const int rowBase = blockIdx.x * 128;

    // fused weight: ws[k*192 + m*64 + c]
    {
        const float* Wm[3] = {Wq, Wk, Wv};
#pragma unroll
        for (int m = 0; m < 3; m++) {
            const float4* src = (const float4*)Wm[m];
            for (int e = tid; e < 1024; e += 256) {
                int k = e >> 4, c4 = e & 15;
                *(float4*)(ws + k * 192 + m * 64 + c4 * 4) = src[e];
            }
        }
    }
    // x tile (zero-pad past N), stride-65 rows
    for (int e = tid; e < 2048; e += 256) {
        int r = e >> 4, c4 = e & 15;
        float4 v = make_float4(0.f, 0.f, 0.f, 0.f);
        if (rowBase + r < N)
            v = *(const float4*)(x + (size_t)(rowBase + r) * 64 + c4 * 4);
        float* d = xs + r * 65 + c4 * 4;
        d[0] = v.x; d[1] = v.y; d[2] = v.z; d[3] = v.w;
    }
    // p repack (rows of this tile)
    if (tid < 128) {
        int row = rowBase + tid;
        if (row < N)
            g_p4[row] = make_float4(p[row * 3], p[row * 3 + 1], p[row * 3 + 2], 0.f);
    }
    __syncthreads();

    const int tx = tid & 15;      // 16 col groups (4 cols per matrix)
    const int ty = tid >> 4;      // 16 row groups (8 rows each)
    const int r0 = ty * 8;
    const int c0 = tx * 4;

    float2 acc[3][8][2];
    {
        const float* bias[3] = {bq, bk, bv};
#pragma unroll
        for (int m = 0; m < 3; m++) {
            float2 bA = *(const float2*)(bias[m] + c0);
            float2 bB = *(const float2*)(bias[m] + c0 + 2);
#pragma unroll
            for (int r = 0; r < 8; r++) { acc[m][r][0] = bA; acc[m][r][1] = bB; }
        }
    }

#pragma unroll 4
    for (int k = 0; k < 64; k++) {
        float xv[8];
#pragma unroll
        for (int r = 0; r < 8; r++) xv[r] = xs[(r0 + r) * 65 + k];
        const float* wk = ws + k * 192 + c0;
#pragma unroll
        for (int m = 0; m < 3; m++) {
            float4 w4 = *(const float4*)(wk + m * 64);
            float2 wA = make_float2(w4.x, w4.y);
            float2 wB = make_float2(w4.z, w4.w);
#pragma unroll
            for (int r = 0; r < 8; r++) {
                float2 xr = make_float2(xv[r], xv[r]);
                acc[m][r][0] = fma2(xr, wA, acc[m][r][0]);
                acc[m][r][1] = fma2(xr, wB, acc[m][r][1]);
            }
        }
    }

    float* outs[3] = {g_q, g_k, g_v};
#pragma unroll
    for (int m = 0; m < 3; m++) {
#pragma unroll
        for (int r = 0; r < 8; r++) {
            int row = rowBase + r0 + r;
            if (row < N)
                *(float4*)(outs[m] + (size_t)row * 64 + c0) =
                    make_float4(acc[m][r][0].x, acc[m][r][0].y,
                                acc[m][r][1].x, acc[m][r][1].y);
        }
    }
}

// ============================================================================
// Kernel 2: fused attention (unchanged from R7 — protected win).
// ============================================================================
struct __align__(16) K2C {
    float s1[64], bb1[64];
    float ws0[64], ws1[64], ws2[64], wsb[64];  // s1-scaled Wp2 rows + s1*bp2
    float r0[64], r1[64], r2[64], rb[64];      // raw Wp2 rows + bp2 (phase B)
    float wa[512];                             // Wa [64][8] (rows 32B-aligned)
    float wbm[64];                             // Wb [8][8]
    float s2[8], bb2[8], ba[8], bw[8];
    float wp1[9], bp1v[3], spv[3], bpv[3];
};

#define RV_J_STRIDE 36          // 32 ch + 4 pad (pad holds h-pack)
#define RV_PT_STRIDE 584        // 16*36 + 8 stagger; % 32 == 8
#define W_J_STRIDE 12           // softmax weight row (8 + 4 gap), 48B

__global__ __launch_bounds__(128, 8) void attn_kernel(
    const int* __restrict__ idx,
    const float* __restrict__ Wp1, const float* __restrict__ bp1,
    const float* __restrict__ gp,  const float* __restrict__ bp,
    const float* __restrict__ Wp2, const float* __restrict__ bp2,
    const float* __restrict__ g1,  const float* __restrict__ bb1,
    const float* __restrict__ Wa,  const float* __restrict__ ba,
    const float* __restrict__ g2,  const float* __restrict__ bb2,
    const float* __restrict__ Wb,  const float* __restrict__ bw,
    float* __restrict__ outp, int N)
{
    __shared__ K2C cst;
    extern __shared__ __align__(16) float rv_s[];  // 8 * RV_PT_STRIDE floats

    const int tid = threadIdx.x;
    const float RSQ = rsqrtf(1.f + 1e-5f);

    // ---- constant prep ----
    if (tid < 64) {
        float s1v = g1[tid] * RSQ;
        cst.s1[tid]  = s1v;
        cst.bb1[tid] = bb1[tid];
        float w0 = Wp2[tid], w1 = Wp2[64 + tid], w2 = Wp2[128 + tid], bb = bp2[tid];
        cst.r0[tid] = w0;        cst.r1[tid] = w1;
        cst.r2[tid] = w2;        cst.rb[tid] = bb;
        cst.ws0[tid] = w0 * s1v; cst.ws1[tid] = w1 * s1v;
        cst.ws2[tid] = w2 * s1v; cst.wsb[tid] = bb * s1v;
        cst.wbm[tid] = Wb[tid];
    }
    for (int e = tid; e < 512; e += 128) cst.wa[e] = Wa[e];
    if (tid < 8) {
        cst.s2[tid] = g2[tid] * RSQ;
        cst.bb2[tid] = bb2[tid];
        cst.ba[tid]  = ba[tid];
        cst.bw[tid]  = bw[tid];
    }
    if (tid >= 64 && tid < 73) cst.wp1[tid - 64] = Wp1[tid - 64];
    if (tid >= 80 && tid < 83) {
        int t = tid - 80;
        cst.bp1v[t] = bp1[t]; cst.spv[t] = gp[t] * RSQ; cst.bpv[t] = bp[t];
    }
    __syncthreads();

    const int pt = tid >> 4;          // 0..7
    const int l  = tid & 15;
    const int i0 = blockIdx.x * 8 + pt;
    const int i  = (i0 < N) ? i0 : 0;   // clamp; final store guarded

    float* rvp = rv_s + pt * RV_PT_STRIDE;

    // ---- prep (lane = neighbor l): nj in register + pe hidden -> pad ----
    const int nj = idx[i * 16 + l];
    {
        float4 pc = g_p4[i];
        float4 pn = g_p4[nj];
        float prx = pn.x - pc.x, pry = pn.y - pc.y, prz = pn.z - pc.z;
        float u0 = cst.bp1v[0] + prx * cst.wp1[0] + pry * cst.wp1[3] + prz * cst.wp1[6];
        float u1 = cst.bp1v[1] + prx * cst.wp1[1] + pry * cst.wp1[4] + prz * cst.wp1[7];
        float u2 = cst.bp1v[2] + prx * cst.wp1[2] + pry * cst.wp1[5] + prz * cst.wp1[8];
        float h0 = fmaxf(fmaf(u0, cst.spv[0], cst.bpv[0]), 0.f);
        float h1 = fmaxf(fmaf(u1, cst.spv[1], cst.bpv[1]), 0.f);
        float h2 = fmaxf(fmaf(u2, cst.spv[2], cst.bpv[2]), 0.f);
        *(float4*)(rvp + l * RV_J_STRIDE + 32) = make_float4(h0, h1, h2, 0.f);
    }
    __syncwarp();

    float2 a2[4];
#pragma unroll
    for (int q = 0; q < 4; q++) a2[q] = *(const float2*)(cst.ba + q * 2);

    // ---- chunked stage + phase A (2 chunks of 32 channels) ----
#pragma unroll
    for (int cb = 0; cb < 64; cb += 32) {
        // stage: lane owns channels (cb+2l, cb+2l+1)
        const int c0 = cb + l * 2;
        float2 s12 = *(const float2*)(cst.s1 + c0);
        float2 xq2;
        {
            float2 q2 = *(const float2*)(g_q + (size_t)i * 64 + c0);
            float2 b2v = *(const float2*)(cst.bb1 + c0);
            xq2.x = fmaf(-q2.x, s12.x, b2v.x);
            xq2.y = fmaf(-q2.y, s12.y, b2v.y);
        }
        float2 w02 = *(const float2*)(cst.ws0 + c0);
        float2 w12 = *(const float2*)(cst.ws1 + c0);
        float2 w22 = *(const float2*)(cst.ws2 + c0);
        float2 wb2 = *(const float2*)(cst.wsb + c0);

#pragma unroll 4
        for (int jj = 0; jj < 16; jj++) {
            int    nb = __shfl_sync(0xffffffffu, nj, jj, 16);        // reg -> LDG addr
            float2 kv = *(const float2*)(g_k + (size_t)nb * 64 + c0);
            float4 h4 = *(const float4*)(rvp + jj * RV_J_STRIDE + 32); // bcast LDS
            float2 pe = fma2(make_float2(h4.x, h4.x), w02,
                        fma2(make_float2(h4.y, h4.y), w12,
                        fma2(make_float2(h4.z, h4.z), w22, wb2)));
            float2 arg = fma2(kv, s12, add2(xq2, pe));
            *(float2*)(rvp + jj * RV_J_STRIDE + l * 2) =
                make_float2(fmaxf(arg.x, 0.f), fmaxf(arg.y, 0.f));
        }
        __syncwarp();

        // phase A partial: lane = neighbor l; channels cb..cb+31
        {
            const float* rvj = rvp + l * RV_J_STRIDE;
#pragma unroll
            for (int c4 = 0; c4 < 8; c4++) {
                float4 rv4 = *(const float4*)(rvj + c4 * 4);
                float rvv[4] = {rv4.x, rv4.y, rv4.z, rv4.w};
#pragma unroll
                for (int ii = 0; ii < 4; ii++) {
                    const float* war = cst.wa + (cb + c4 * 4 + ii) * 8;
                    float4 wa0 = *(const float4*)(war);
                    float4 wa1 = *(const float4*)(war + 4);
                    float2 rr = make_float2(rvv[ii], rvv[ii]);
                    a2[0] = fma2(rr, make_float2(wa0.x, wa0.y), a2[0]);
                    a2[1] = fma2(rr, make_float2(wa0.z, wa0.w), a2[1]);
                    a2[2] = fma2(rr, make_float2(wa1.x, wa1.y), a2[2]);
                    a2[3] = fma2(rr, make_float2(wa1.z, wa1.w), a2[3]);
                }
            }
        }
        __syncwarp();
    }

    // ---- second MLP (8 -> 8) ----
    float2 b2[4];
#pragma unroll
    for (int q = 0; q < 4; q++) b2[q] = *(const float2*)(cst.bw + q * 2);
#pragma unroll
    for (int m = 0; m < 8; m++) {
        float avm = (m & 1) ? a2[m >> 1].y : a2[m >> 1].x;
        float t = fmaxf(fmaf(avm, cst.s2[m], cst.bb2[m]), 0.f);
        float2 tt = make_float2(t, t);
        const float2* wr = (const float2*)(cst.wbm + m * 8);
        b2[0] = fma2(tt, wr[0], b2[0]);
        b2[1] = fma2(tt, wr[1], b2[1]);
        b2[2] = fma2(tt, wr[2], b2[2]);
        b2[3] = fma2(tt, wr[3], b2[3]);
    }

    // ---- softmax over 16 neighbors, in place in b2 ----
    {
#pragma unroll
        for (int q = 0; q < 4; q++) {
            float2 v2 = b2[q];
            float mx0 = v2.x, mx1 = v2.y;
#pragma unroll
            for (int off = 8; off >= 1; off >>= 1) {
                mx0 = fmaxf(mx0, __shfl_xor_sync(0xffffffffu, mx0, off));
                mx1 = fmaxf(mx1, __shfl_xor_sync(0xffffffffu, mx1, off));
            }
            float e0 = __expf(v2.x - mx0);
            float e1 = __expf(v2.y - mx1);
            float s0 = e0, s1 = e1;
#pragma unroll
            for (int off = 8; off >= 1; off >>= 1) {
                s0 += __shfl_xor_sync(0xffffffffu, s0, off);
                s1 += __shfl_xor_sync(0xffffffffu, s1, off);
            }
            b2[q] = make_float2(__fdividef(e0, s0), __fdividef(e1, s1));
        }
    }
    // overlay softmax weights into dead rv words 12l..12l+7 (disjoint from h-pack)
    {
        float* wp = rvp + l * W_J_STRIDE;
        *(float4*)(wp)     = make_float4(b2[0].x, b2[0].y, b2[1].x, b2[1].y);
        *(float4*)(wp + 4) = make_float4(b2[2].x, b2[2].y, b2[3].x, b2[3].y);
    }
    __syncwarp();

    // ---- phase B: channel-parallel aggregation (coalesced v gather) ----
    const int c0 = l * 4;
    const int m0 = (l & 1) * 4;
    float4 rr0 = *(const float4*)(cst.r0 + c0);
    float4 rr1 = *(const float4*)(cst.r1 + c0);
    float4 rr2 = *(const float4*)(cst.r2 + c0);
    float4 rrb = *(const float4*)(cst.rb + c0);
    float2 acc01 = make_float2(0.f, 0.f), acc23 = make_float2(0.f, 0.f);
#pragma unroll 4
    for (int jj = 0; jj < 16; jj++) {
        int    nb = __shfl_sync(0xffffffffu, nj, jj, 16);          // reg -> LDG addr
        float4 v4 = *(const float4*)(g_v + (size_t)nb * 64 + c0);
        float4 h4 = *(const float4*)(rvp + jj * RV_J_STRIDE + 32); // bcast LDS
        float4 wv = *(const float4*)(rvp + jj * W_J_STRIDE + m0);
        float2 pe01 = fma2(make_float2(h4.x, h4.x), make_float2(rr0.x, rr0.y),
                      fma2(make_float2(h4.y, h4.y), make_float2(rr1.x, rr1.y),
                      fma2(make_float2(h4.z, h4.z), make_float2(rr2.x, rr2.y),
                           make_float2(rrb.x, rrb.y))));
        float2 pe23 = fma2(make_float2(h4.x, h4.x), make_float2(rr0.z, rr0.w),
                      fma2(make_float2(h4.y, h4.y), make_float2(rr1.z, rr1.w),
                      fma2(make_float2(h4.z, h4.z), make_float2(rr2.z, rr2.w),
                           make_float2(rrb.z, rrb.w))));
        acc01 = fma2(add2(make_float2(v4.x, v4.y), pe01), make_float2(wv.x, wv.y), acc01);
        acc23 = fma2(add2(make_float2(v4.z, v4.w), pe23), make_float2(wv.z, wv.w), acc23);
    }
    if (i0 < N)
        *(float4*)(outp + (size_t)i0 * 64 + c0) =
            make_float4(acc01.x, acc01.y, acc23.x, acc23.y);
}

// ============================================================================
extern "C" void kernel_launch(void* const* d_in, const int* in_sizes, int n_in,
                              void* d_out, int out_size) {
    const float* p   = (const float*)d_in[0];
    const float* x   = (const float*)d_in[1];
    const int*   idx = (const int*)d_in[2];
    const float* Wq  = (const float*)d_in[3];  const float* bq  = (const float*)d_in[4];
    const float* Wk  = (const float*)d_in[5];  const float* bk  = (const float*)d_in[6];
    const float* Wv  = (const float*)d_in[7];  const float* bv  = (const float*)d_in[8];
    const float* Wp1 = (const float*)d_in[9];  const float* bp1 = (const float*)d_in[10];
    const float* gp  = (const float*)d_in[11]; const float* bp  = (const float*)d_in[12];
    const float* Wp2 = (const float*)d_in[13]; const float* bp2 = (const float*)d_in[14];
    const float* g1  = (const float*)d_in[15]; const float* bb1 = (const float*)d_in[16];
    const float* Wa  = (const float*)d_in[17]; const float* ba  = (const float*)d_in[18];
    const float* g2  = (const float*)d_in[19]; const float* bb2 = (const float*)d_in[20];
    const float* Wb  = (const float*)d_in[21]; const float* bw  = (const float*)d_in[22];

    int N = in_sizes[0] / 3;
    if (N > MAXN) N = MAXN;  // scratch bound (problem shape is N=100000)

    const int qkv_dyn  = (128 * 65 + 64 * 192) * (int)sizeof(float);  // 82432
    const int attn_dyn = 8 * RV_PT_STRIDE * (int)sizeof(float);       // 18688
    cudaFuncSetAttribute(qkv_kernel,  cudaFuncAttributeMaxDynamicSharedMemorySize, qkv_dyn);
    cudaFuncSetAttribute(attn_kernel, cudaFuncAttributeMaxDynamicSharedMemorySize, attn_dyn);

    qkv_kernel<<<(N + 127) / 128, 256, qkv_dyn>>>(x, p, Wq, bq, Wk, bk, Wv, bv, N);

    attn_kernel<<<(N + 7) / 8, 128, attn_dyn>>>(idx, Wp1, bp1, gp, bp, Wp2, bp2,
                                                g1, bb1, Wa, ba, g2, bb2, Wb, bw,
                                                (float*)d_out, N);
}

// round 10
// speedup vs baseline: 1.1160x; 1.1160x over previous
#include <cuda_runtime.h>
#include <cstdint>
#include <cstddef>

#define MAXN 131072

// scratch (device globals: no allocation allowed)
__device__ float g_q[MAXN * 64];
__device__ float g_k[MAXN * 64];
__device__ float g_v[MAXN * 64];
__device__ float4 g_p4[MAXN];

// ---- packed fp32x2 ops (sm_103a FFMA2 path) ----
__device__ __forceinline__ float2 fma2(float2 a, float2 b, float2 c) {
    float2 d;
    asm("fma.rn.f32x2 %0, %1, %2, %3;"
        : "=l"(*(unsigned long long*)&d)
        : "l"(*(unsigned long long*)&a),
          "l"(*(unsigned long long*)&b),
          "l"(*(unsigned long long*)&c));
    return d;
}
__device__ __forceinline__ float2 add2(float2 a, float2 b) {
    float2 d;
    asm("add.rn.f32x2 %0, %1, %2;"
        : "=l"(*(unsigned long long*)&d)
        : "l"(*(unsigned long long*)&a),
          "l"(*(unsigned long long*)&b));
    return d;
}

// ============================================================================
// Kernel 1: fused q/k/v = x @ [Wq|Wk|Wv] + b, plus p -> g_p4 repack.
// 64-row tile; thread = 4 rows x (3 matrices x 4 cols)  [R7 geometry, regs~64]
// x tile stored TRANSPOSED xT[k][row] (stride 68) with rotation swizzle
// off = (r + 4*(k>>3)) & 63 -> inner-loop x read is ONE LDS.128 (1 phase)
// instead of 4 scalar LDS; store side stays 2-phase. 16B alignment holds
// (stride 68 and offsets are multiples of 4 words).
// ============================================================================
__global__ __launch_bounds__(256) void qkv_kernel(
    const float* __restrict__ x, const float* __restrict__ p,
    const float* __restrict__ Wq, const float* __restrict__ bq,
    const float* __restrict__ Wk, const float* __restrict__ bk,
    const float* __restrict__ Wv, const float* __restrict__ bv,
    int N)
{
    extern __shared__ float smem[];
    float* xT = smem;                  // 64 k-rows * 68 = 4352 floats
    float* ws = smem + 4352;           // 64*192 = 12288 floats
    const int tid = threadIdx.x;
    const int rowBase = blockIdx.x * 64;

    // fused weight: ws[k*192 + m*64 + c]
    {
        const float* Wm[3] = {Wq, Wk, Wv};
#pragma unroll
        for (int m = 0; m < 3; m++) {
            const float4* src = (const float4*)Wm[m];
            for (int e = tid; e < 1024; e += 256) {
                int k = e >> 4, c4 = e & 15;
                *(float4*)(ws + k * 192 + m * 64 + c4 * 4) = src[e];
            }
        }
    }
    // x tile, transposed + swizzled (zero-pad past N)
    for (int e = tid; e < 1024; e += 256) {
        int r = e >> 4, c4 = e & 15;
        float4 v = make_float4(0.f, 0.f, 0.f, 0.f);
        if (rowBase + r < N)
            v = *(const float4*)(x + (size_t)(rowBase + r) * 64 + c4 * 4);
        int k0 = c4 * 4;
        float vv[4] = {v.x, v.y, v.z, v.w};
#pragma unroll
        for (int j = 0; j < 4; j++) {
            int k = k0 + j;
            int off = (r + ((k >> 3) << 2)) & 63;
            xT[k * 68 + off] = vv[j];
        }
    }
    // p repack (rows of this tile)
    if (tid < 64) {
        int row = rowBase + tid;
        if (row < N)
            g_p4[row] = make_float4(p[row * 3], p[row * 3 + 1], p[row * 3 + 2], 0.f);
    }
    __syncthreads();

    const int tx = tid & 15;      // 16 col groups (4 cols per matrix)
    const int ty = tid >> 4;      // 16 row groups (4 rows each)
    const int r0 = ty * 4;
    const int c0 = tx * 4;

    float2 acc[3][4][2];
    {
        const float* bias[3] = {bq, bk, bv};
#pragma unroll
        for (int m = 0; m < 3; m++) {
            float2 bA = *(const float2*)(bias[m] + c0);
            float2 bB = *(const float2*)(bias[m] + c0 + 2);
#pragma unroll
            for (int r = 0; r < 4; r++) { acc[m][r][0] = bA; acc[m][r][1] = bB; }
        }
    }

#pragma unroll 8
    for (int k = 0; k < 64; k++) {
        // rows r0..r0+3 at input-channel k: ONE swizzled LDS.128
        int off = (r0 + ((k >> 3) << 2)) & 63;
        float4 x4 = *(const float4*)(xT + k * 68 + off);
        float xv[4] = {x4.x, x4.y, x4.z, x4.w};
        const float* wk = ws + k * 192 + c0;
#pragma unroll
        for (int m = 0; m < 3; m++) {
            float4 w4 = *(const float4*)(wk + m * 64);
            float2 wA = make_float2(w4.x, w4.y);
            float2 wB = make_float2(w4.z, w4.w);
#pragma unroll
            for (int r = 0; r < 4; r++) {
                float2 xr = make_float2(xv[r], xv[r]);
                acc[m][r][0] = fma2(xr, wA, acc[m][r][0]);
                acc[m][r][1] = fma2(xr, wB, acc[m][r][1]);
            }
        }
    }

    float* outs[3] = {g_q, g_k, g_v};
#pragma unroll
    for (int m = 0; m < 3; m++) {
#pragma unroll
        for (int r = 0; r < 4; r++) {
            int row = rowBase + r0 + r;
            if (row < N)
                *(float4*)(outs[m] + (size_t)row * 64 + c0) =
                    make_float4(acc[m][r][0].x, acc[m][r][0].y,
                                acc[m][r][1].x, acc[m][r][1].y);
        }
    }
}

// ============================================================================
// Kernel 2: fused attention (unchanged from R7 — protected win).
// ============================================================================
struct __align__(16) K2C {
    float s1[64], bb1[64];
    float ws0[64], ws1[64], ws2[64], wsb[64];  // s1-scaled Wp2 rows + s1*bp2
    float r0[64], r1[64], r2[64], rb[64];      // raw Wp2 rows + bp2 (phase B)
    float wa[512];                             // Wa [64][8] (rows 32B-aligned)
    float wbm[64];                             // Wb [8][8]
    float s2[8], bb2[8], ba[8], bw[8];
    float wp1[9], bp1v[3], spv[3], bpv[3];
};

#define RV_J_STRIDE 36          // 32 ch + 4 pad (pad holds h-pack)
#define RV_PT_STRIDE 584        // 16*36 + 8 stagger; % 32 == 8
#define W_J_STRIDE 12           // softmax weight row (8 + 4 gap), 48B

__global__ __launch_bounds__(128, 8) void attn_kernel(
    const int* __restrict__ idx,
    const float* __restrict__ Wp1, const float* __restrict__ bp1,
    const float* __restrict__ gp,  const float* __restrict__ bp,
    const float* __restrict__ Wp2, const float* __restrict__ bp2,
    const float* __restrict__ g1,  const float* __restrict__ bb1,
    const float* __restrict__ Wa,  const float* __restrict__ ba,
    const float* __restrict__ g2,  const float* __restrict__ bb2,
    const float* __restrict__ Wb,  const float* __restrict__ bw,
    float* __restrict__ outp, int N)
{
    __shared__ K2C cst;
    extern __shared__ __align__(16) float rv_s[];  // 8 * RV_PT_STRIDE floats

    const int tid = threadIdx.x;
    const float RSQ = rsqrtf(1.f + 1e-5f);

    // ---- constant prep ----
    if (tid < 64) {
        float s1v = g1[tid] * RSQ;
        cst.s1[tid]  = s1v;
        cst.bb1[tid] = bb1[tid];
        float w0 = Wp2[tid], w1 = Wp2[64 + tid], w2 = Wp2[128 + tid], bb = bp2[tid];
        cst.r0[tid] = w0;        cst.r1[tid] = w1;
        cst.r2[tid] = w2;        cst.rb[tid] = bb;
        cst.ws0[tid] = w0 * s1v; cst.ws1[tid] = w1 * s1v;
        cst.ws2[tid] = w2 * s1v; cst.wsb[tid] = bb * s1v;
        cst.wbm[tid] = Wb[tid];
    }
    for (int e = tid; e < 512; e += 128) cst.wa[e] = Wa[e];
    if (tid < 8) {
        cst.s2[tid] = g2[tid] * RSQ;
        cst.bb2[tid] = bb2[tid];
        cst.ba[tid]  = ba[tid];
        cst.bw[tid]  = bw[tid];
    }
    if (tid >= 64 && tid < 73) cst.wp1[tid - 64] = Wp1[tid - 64];
    if (tid >= 80 && tid < 83) {
        int t = tid - 80;
        cst.bp1v[t] = bp1[t]; cst.spv[t] = gp[t] * RSQ; cst.bpv[t] = bp[t];
    }
    __syncthreads();

    const int pt = tid >> 4;          // 0..7
    const int l  = tid & 15;
    const int i0 = blockIdx.x * 8 + pt;
    const int i  = (i0 < N) ? i0 : 0;   // clamp; final store guarded

    float* rvp = rv_s + pt * RV_PT_STRIDE;

    // ---- prep (lane = neighbor l): nj in register + pe hidden -> pad ----
    const int nj = idx[i * 16 + l];
    {
        float4 pc = g_p4[i];
        float4 pn = g_p4[nj];
        float prx = pn.x - pc.x, pry = pn.y - pc.y, prz = pn.z - pc.z;
        float u0 = cst.bp1v[0] + prx * cst.wp1[0] + pry * cst.wp1[3] + prz * cst.wp1[6];
        float u1 = cst.bp1v[1] + prx * cst.wp1[1] + pry * cst.wp1[4] + prz * cst.wp1[7];
        float u2 = cst.bp1v[2] + prx * cst.wp1[2] + pry * cst.wp1[5] + prz * cst.wp1[8];
        float h0 = fmaxf(fmaf(u0, cst.spv[0], cst.bpv[0]), 0.f);
        float h1 = fmaxf(fmaf(u1, cst.spv[1], cst.bpv[1]), 0.f);
        float h2 = fmaxf(fmaf(u2, cst.spv[2], cst.bpv[2]), 0.f);
        *(float4*)(rvp + l * RV_J_STRIDE + 32) = make_float4(h0, h1, h2, 0.f);
    }
    __syncwarp();

    float2 a2[4];
#pragma unroll
    for (int q = 0; q < 4; q++) a2[q] = *(const float2*)(cst.ba + q * 2);

    // ---- chunked stage + phase A (2 chunks of 32 channels) ----
#pragma unroll
    for (int cb = 0; cb < 64; cb += 32) {
        // stage: lane owns channels (cb+2l, cb+2l+1)
        const int c0 = cb + l * 2;
        float2 s12 = *(const float2*)(cst.s1 + c0);
        float2 xq2;
        {
            float2 q2 = *(const float2*)(g_q + (size_t)i * 64 + c0);
            float2 b2v = *(const float2*)(cst.bb1 + c0);
            xq2.x = fmaf(-q2.x, s12.x, b2v.x);
            xq2.y = fmaf(-q2.y, s12.y, b2v.y);
        }
        float2 w02 = *(const float2*)(cst.ws0 + c0);
        float2 w12 = *(const float2*)(cst.ws1 + c0);
        float2 w22 = *(const float2*)(cst.ws2 + c0);
        float2 wb2 = *(const float2*)(cst.wsb + c0);

#pragma unroll 4
        for (int jj = 0; jj < 16; jj++) {
            int    nb = __shfl_sync(0xffffffffu, nj, jj, 16);        // reg -> LDG addr
            float2 kv = *(const float2*)(g_k + (size_t)nb * 64 + c0);
            float4 h4 = *(const float4*)(rvp + jj * RV_J_STRIDE + 32); // bcast LDS
            float2 pe = fma2(make_float2(h4.x, h4.x), w02,
                        fma2(make_float2(h4.y, h4.y), w12,
                        fma2(make_float2(h4.z, h4.z), w22, wb2)));
            float2 arg = fma2(kv, s12, add2(xq2, pe));
            *(float2*)(rvp + jj * RV_J_STRIDE + l * 2) =
                make_float2(fmaxf(arg.x, 0.f), fmaxf(arg.y, 0.f));
        }
        __syncwarp();

        // phase A partial: lane = neighbor l; channels cb..cb+31
        {
            const float* rvj = rvp + l * RV_J_STRIDE;
#pragma unroll
            for (int c4 = 0; c4 < 8; c4++) {
                float4 rv4 = *(const float4*)(rvj + c4 * 4);
                float rvv[4] = {rv4.x, rv4.y, rv4.z, rv4.w};
#pragma unroll
                for (int ii = 0; ii < 4; ii++) {
                    const float* war = cst.wa + (cb + c4 * 4 + ii) * 8;
                    float4 wa0 = *(const float4*)(war);
                    float4 wa1 = *(const float4*)(war + 4);
                    float2 rr = make_float2(rvv[ii], rvv[ii]);
                    a2[0] = fma2(rr, make_float2(wa0.x, wa0.y), a2[0]);
                    a2[1] = fma2(rr, make_float2(wa0.z, wa0.w), a2[1]);
                    a2[2] = fma2(rr, make_float2(wa1.x, wa1.y), a2[2]);
                    a2[3] = fma2(rr, make_float2(wa1.z, wa1.w), a2[3]);
                }
            }
        }
        __syncwarp();
    }

    // ---- second MLP (8 -> 8) ----
    float2 b2[4];
#pragma unroll
    for (int q = 0; q < 4; q++) b2[q] = *(const float2*)(cst.bw + q * 2);
#pragma unroll
    for (int m = 0; m < 8; m++) {
        float avm = (m & 1) ? a2[m >> 1].y : a2[m >> 1].x;
        float t = fmaxf(fmaf(avm, cst.s2[m], cst.bb2[m]), 0.f);
        float2 tt = make_float2(t, t);
        const float2* wr = (const float2*)(cst.wbm + m * 8);
        b2[0] = fma2(tt, wr[0], b2[0]);
        b2[1] = fma2(tt, wr[1], b2[1]);
        b2[2] = fma2(tt, wr[2], b2[2]);
        b2[3] = fma2(tt, wr[3], b2[3]);
    }

    // ---- softmax over 16 neighbors, in place in b2 ----
    {
#pragma unroll
        for (int q = 0; q < 4; q++) {
            float2 v2 = b2[q];
            float mx0 = v2.x, mx1 = v2.y;
#pragma unroll
            for (int off = 8; off >= 1; off >>= 1) {
                mx0 = fmaxf(mx0, __shfl_xor_sync(0xffffffffu, mx0, off));
                mx1 = fmaxf(mx1, __shfl_xor_sync(0xffffffffu, mx1, off));
            }
            float e0 = __expf(v2.x - mx0);
            float e1 = __expf(v2.y - mx1);
            float s0 = e0, s1 = e1;
#pragma unroll
            for (int off = 8; off >= 1; off >>= 1) {
                s0 += __shfl_xor_sync(0xffffffffu, s0, off);
                s1 += __shfl_xor_sync(0xffffffffu, s1, off);
            }
            b2[q] = make_float2(__fdividef(e0, s0), __fdividef(e1, s1));
        }
    }
    // overlay softmax weights into dead rv words 12l..12l+7 (disjoint from h-pack)
    {
        float* wp = rvp + l * W_J_STRIDE;
        *(float4*)(wp)     = make_float4(b2[0].x, b2[0].y, b2[1].x, b2[1].y);
        *(float4*)(wp + 4) = make_float4(b2[2].x, b2[2].y, b2[3].x, b2[3].y);
    }
    __syncwarp();

    // ---- phase B: channel-parallel aggregation (coalesced v gather) ----
    const int c0 = l * 4;
    const int m0 = (l & 1) * 4;
    float4 rr0 = *(const float4*)(cst.r0 + c0);
    float4 rr1 = *(const float4*)(cst.r1 + c0);
    float4 rr2 = *(const float4*)(cst.r2 + c0);
    float4 rrb = *(const float4*)(cst.rb + c0);
    float2 acc01 = make_float2(0.f, 0.f), acc23 = make_float2(0.f, 0.f);
#pragma unroll 4
    for (int jj = 0; jj < 16; jj++) {
        int    nb = __shfl_sync(0xffffffffu, nj, jj, 16);          // reg -> LDG addr
        float4 v4 = *(const float4*)(g_v + (size_t)nb * 64 + c0);
        float4 h4 = *(const float4*)(rvp + jj * RV_J_STRIDE + 32); // bcast LDS
        float4 wv = *(const float4*)(rvp + jj * W_J_STRIDE + m0);
        float2 pe01 = fma2(make_float2(h4.x, h4.x), make_float2(rr0.x, rr0.y),
                      fma2(make_float2(h4.y, h4.y), make_float2(rr1.x, rr1.y),
                      fma2(make_float2(h4.z, h4.z), make_float2(rr2.x, rr2.y),
                           make_float2(rrb.x, rrb.y))));
        float2 pe23 = fma2(make_float2(h4.x, h4.x), make_float2(rr0.z, rr0.w),
                      fma2(make_float2(h4.y, h4.y), make_float2(rr1.z, rr1.w),
                      fma2(make_float2(h4.z, h4.z), make_float2(rr2.z, rr2.w),
                           make_float2(rrb.z, rrb.w))));
        acc01 = fma2(add2(make_float2(v4.x, v4.y), pe01), make_float2(wv.x, wv.y), acc01);
        acc23 = fma2(add2(make_float2(v4.z, v4.w), pe23), make_float2(wv.z, wv.w), acc23);
    }
    if (i0 < N)
        *(float4*)(outp + (size_t)i0 * 64 + c0) =
            make_float4(acc01.x, acc01.y, acc23.x, acc23.y);
}

// ============================================================================
extern "C" void kernel_launch(void* const* d_in, const int* in_sizes, int n_in,
                              void* d_out, int out_size) {
    const float* p   = (const float*)d_in[0];
    const float* x   = (const float*)d_in[1];
    const int*   idx = (const int*)d_in[2];
    const float* Wq  = (const float*)d_in[3];  const float* bq  = (const float*)d_in[4];
    const float* Wk  = (const float*)d_in[5];  const float* bk  = (const float*)d_in[6];
    const float* Wv  = (const float*)d_in[7];  const float* bv  = (const float*)d_in[8];
    const float* Wp1 = (const float*)d_in[9];  const float* bp1 = (const float*)d_in[10];
    const float* gp  = (const float*)d_in[11]; const float* bp  = (const float*)d_in[12];
    const float* Wp2 = (const float*)d_in[13]; const float* bp2 = (const float*)d_in[14];
    const float* g1  = (const float*)d_in[15]; const float* bb1 = (const float*)d_in[16];
    const float* Wa  = (const float*)d_in[17]; const float* ba  = (const float*)d_in[18];
    const float* g2  = (const float*)d_in[19]; const float* bb2 = (const float*)d_in[20];
    const float* Wb  = (const float*)d_in[21]; const float* bw  = (const float*)d_in[22];

    int N = in_sizes[0] / 3;
    if (N > MAXN) N = MAXN;  // scratch bound (problem shape is N=100000)

    const int qkv_dyn  = (64 * 68 + 64 * 192) * (int)sizeof(float);  // 66560
    const int attn_dyn = 8 * RV_PT_STRIDE * (int)sizeof(float);      // 18688
    cudaFuncSetAttribute(qkv_kernel,  cudaFuncAttributeMaxDynamicSharedMemorySize, qkv_dyn);
    cudaFuncSetAttribute(attn_kernel, cudaFuncAttributeMaxDynamicSharedMemorySize, attn_dyn);

    qkv_kernel<<<(N + 63) / 64, 256, qkv_dyn>>>(x, p, Wq, bq, Wk, bk, Wv, bv, N);

    attn_kernel<<<(N + 7) / 8, 128, attn_dyn>>>(idx, Wp1, bp1, gp, bp, Wp2, bp2,
                                                g1, bb1, Wa, ba, g2, bb2, Wb, bw,
                                                (float*)d_out, N);
}

// round 11
// speedup vs baseline: 1.1933x; 1.0692x over previous
#include <cuda_runtime.h>
#include <cstdint>
#include <cstddef>

#define MAXN 131072

// scratch (device globals: no allocation allowed)
__device__ float g_q[MAXN * 64];
__device__ float g_k[MAXN * 64];
__device__ float g_v[MAXN * 64];
__device__ float4 g_p4[MAXN];

// ---- packed fp32x2 ops (sm_103a FFMA2 path) ----
__device__ __forceinline__ float2 fma2(float2 a, float2 b, float2 c) {
    float2 d;
    asm("fma.rn.f32x2 %0, %1, %2, %3;"
        : "=l"(*(unsigned long long*)&d)
        : "l"(*(unsigned long long*)&a),
          "l"(*(unsigned long long*)&b),
          "l"(*(unsigned long long*)&c));
    return d;
}
__device__ __forceinline__ float2 add2(float2 a, float2 b) {
    float2 d;
    asm("add.rn.f32x2 %0, %1, %2;"
        : "=l"(*(unsigned long long*)&d)
        : "l"(*(unsigned long long*)&a),
          "l"(*(unsigned long long*)&b));
    return d;
}

// ---- tf32 helpers ----
__device__ __forceinline__ float to_tf32(float f) {
    uint32_t u;
    asm("cvt.rna.tf32.f32 %0, %1;" : "=r"(u) : "f"(f));
    return __uint_as_float(u);
}
__device__ __forceinline__ void mma_tf32(float4& d, const uint32_t* a,
                                         uint32_t b0, uint32_t b1) {
    asm volatile(
        "mma.sync.aligned.m16n8k8.row.col.f32.tf32.tf32.f32 "
        "{%0,%1,%2,%3}, {%4,%5,%6,%7}, {%8,%9}, {%0,%1,%2,%3};"
        : "+f"(d.x), "+f"(d.y), "+f"(d.z), "+f"(d.w)
        : "r"(a[0]), "r"(a[1]), "r"(a[2]), "r"(a[3]), "r"(b0), "r"(b1));
}

// ============================================================================
// Kernel 1: fused q/k/v = x @ [Wq|Wk|Wv] + b via tensor cores (tf32 HMMA),
// plus p -> g_p4 repack. 64-row x 192-col tile per 256-thread block.
// Warp w: rows (w&1)*32 (2 m16 rowsets), cols (w>>1)*48 (6 n8 tiles).
// Smem strides: x 68 (A-frag banks 4q+c distinct), W 200 (B-frag 8c+q
// distinct) -> all fragment LDS conflict-free. Bias folded into C init.
// ============================================================================
#define XS_STRIDE 68
#define WS_STRIDE 200

__global__ __launch_bounds__(256) void qkv_kernel(
    const float* __restrict__ x, const float* __restrict__ p,
    const float* __restrict__ Wq, const float* __restrict__ bq,
    const float* __restrict__ Wk, const float* __restrict__ bk,
    const float* __restrict__ Wv, const float* __restrict__ bv,
    int N)
{
    extern __shared__ float smem[];
    float* xs = smem;                         // 64 * 68 floats (tf32 values)
    float* ws = smem + 64 * XS_STRIDE;        // 64 * 200 floats (tf32 values)
    const int tid = threadIdx.x;
    const int rowBase = blockIdx.x * 64;

    // fused weight (tf32-converted): ws[k*200 + m*64 + c]
    {
        const float* Wm[3] = {Wq, Wk, Wv};
#pragma unroll
        for (int m = 0; m < 3; m++) {
            const float4* src = (const float4*)Wm[m];
            for (int e = tid; e < 1024; e += 256) {
                int k = e >> 4, c4 = e & 15;
                float4 v = src[e];
                v.x = to_tf32(v.x); v.y = to_tf32(v.y);
                v.z = to_tf32(v.z); v.w = to_tf32(v.w);
                *(float4*)(ws + k * WS_STRIDE + m * 64 + c4 * 4) = v;
            }
        }
    }
    // x tile (tf32-converted, zero-pad past N)
    for (int e = tid; e < 1024; e += 256) {
        int r = e >> 4, c4 = e & 15;
        float4 v = make_float4(0.f, 0.f, 0.f, 0.f);
        if (rowBase + r < N) {
            v = *(const float4*)(x + (size_t)(rowBase + r) * 64 + c4 * 4);
            v.x = to_tf32(v.x); v.y = to_tf32(v.y);
            v.z = to_tf32(v.z); v.w = to_tf32(v.w);
        }
        *(float4*)(xs + r * XS_STRIDE + c4 * 4) = v;
    }
    // p repack (rows of this tile)
    if (tid < 64) {
        int row = rowBase + tid;
        if (row < N)
            g_p4[row] = make_float4(p[row * 3], p[row * 3 + 1], p[row * 3 + 2], 0.f);
    }
    __syncthreads();

    const int lane  = tid & 31;
    const int warp  = tid >> 5;
    const int rbase = (warp & 1) * 32;        // 2 row groups of 32
    const int cwb   = (warp >> 1) * 48;       // 4 col groups of 48 (6 n8 tiles)
    const int qd    = lane >> 2;              // 0..7
    const int cl    = lane & 3;               // 0..3

    // C frags, bias-initialized: c0/c2 -> col g, c1/c3 -> col g+1
    const float* bias[3] = {bq, bk, bv};
    float4 C[2][6];
#pragma unroll
    for (int rt = 0; rt < 2; rt++)
#pragma unroll
        for (int t = 0; t < 6; t++) {
            int g = cwb + t * 8 + 2 * cl;
            float b0v = bias[g >> 6][g & 63];
            float b1v = bias[g >> 6][(g & 63) + 1];
            C[rt][t] = make_float4(b0v, b1v, b0v, b1v);
        }

#pragma unroll
    for (int ks = 0; ks < 8; ks++) {
        const int k0 = ks * 8;
        uint32_t a[2][4];
#pragma unroll
        for (int rt = 0; rt < 2; rt++) {
            int r = rbase + rt * 16 + qd;
            a[rt][0] = __float_as_uint(xs[r * XS_STRIDE + k0 + cl]);
            a[rt][1] = __float_as_uint(xs[(r + 8) * XS_STRIDE + k0 + cl]);
            a[rt][2] = __float_as_uint(xs[r * XS_STRIDE + k0 + cl + 4]);
            a[rt][3] = __float_as_uint(xs[(r + 8) * XS_STRIDE + k0 + cl + 4]);
        }
#pragma unroll
        for (int t = 0; t < 6; t++) {
            int n0 = cwb + t * 8;
            uint32_t b0 = __float_as_uint(ws[(k0 + cl) * WS_STRIDE + n0 + qd]);
            uint32_t b1 = __float_as_uint(ws[(k0 + cl + 4) * WS_STRIDE + n0 + qd]);
            mma_tf32(C[0][t], a[0], b0, b1);
            mma_tf32(C[1][t], a[1], b0, b1);
        }
    }

    // epilogue: frag -> gmem (STG.64 pairs), bias already in C
    float* outs[3] = {g_q, g_k, g_v};
#pragma unroll
    for (int rt = 0; rt < 2; rt++) {
        int row0 = rowBase + rbase + rt * 16 + qd;
        int row1 = row0 + 8;
#pragma unroll
        for (int t = 0; t < 6; t++) {
            int g   = cwb + t * 8 + 2 * cl;
            int mat = g >> 6, cc = g & 63;
            float* o = outs[mat];
            if (row0 < N)
                *(float2*)(o + (size_t)row0 * 64 + cc) = make_float2(C[rt][t].x, C[rt][t].y);
            if (row1 < N)
                *(float2*)(o + (size_t)row1 * 64 + cc) = make_float2(C[rt][t].z, C[rt][t].w);
        }
    }
}

// ============================================================================
// Kernel 2: fused attention (unchanged from R7 — protected win).
// ============================================================================
struct __align__(16) K2C {
    float s1[64], bb1[64];
    float ws0[64], ws1[64], ws2[64], wsb[64];  // s1-scaled Wp2 rows + s1*bp2
    float r0[64], r1[64], r2[64], rb[64];      // raw Wp2 rows + bp2 (phase B)
    float wa[512];                             // Wa [64][8] (rows 32B-aligned)
    float wbm[64];                             // Wb [8][8]
    float s2[8], bb2[8], ba[8], bw[8];
    float wp1[9], bp1v[3], spv[3], bpv[3];
};

#define RV_J_STRIDE 36          // 32 ch + 4 pad (pad holds h-pack)
#define RV_PT_STRIDE 584        // 16*36 + 8 stagger; % 32 == 8
#define W_J_STRIDE 12           // softmax weight row (8 + 4 gap), 48B

__global__ __launch_bounds__(128, 8) void attn_kernel(
    const int* __restrict__ idx,
    const float* __restrict__ Wp1, const float* __restrict__ bp1,
    const float* __restrict__ gp,  const float* __restrict__ bp,
    const float* __restrict__ Wp2, const float* __restrict__ bp2,
    const float* __restrict__ g1,  const float* __restrict__ bb1,
    const float* __restrict__ Wa,  const float* __restrict__ ba,
    const float* __restrict__ g2,  const float* __restrict__ bb2,
    const float* __restrict__ Wb,  const float* __restrict__ bw,
    float* __restrict__ outp, int N)
{
    __shared__ K2C cst;
    extern __shared__ __align__(16) float rv_s[];  // 8 * RV_PT_STRIDE floats

    const int tid = threadIdx.x;
    const float RSQ = rsqrtf(1.f + 1e-5f);

    // ---- constant prep ----
    if (tid < 64) {
        float s1v = g1[tid] * RSQ;
        cst.s1[tid]  = s1v;
        cst.bb1[tid] = bb1[tid];
        float w0 = Wp2[tid], w1 = Wp2[64 + tid], w2 = Wp2[128 + tid], bb = bp2[tid];
        cst.r0[tid] = w0;        cst.r1[tid] = w1;
        cst.r2[tid] = w2;        cst.rb[tid] = bb;
        cst.ws0[tid] = w0 * s1v; cst.ws1[tid] = w1 * s1v;
        cst.ws2[tid] = w2 * s1v; cst.wsb[tid] = bb * s1v;
        cst.wbm[tid] = Wb[tid];
    }
    for (int e = tid; e < 512; e += 128) cst.wa[e] = Wa[e];
    if (tid < 8) {
        cst.s2[tid] = g2[tid] * RSQ;
        cst.bb2[tid] = bb2[tid];
        cst.ba[tid]  = ba[tid];
        cst.bw[tid]  = bw[tid];
    }
    if (tid >= 64 && tid < 73) cst.wp1[tid - 64] = Wp1[tid - 64];
    if (tid >= 80 && tid < 83) {
        int t = tid - 80;
        cst.bp1v[t] = bp1[t]; cst.spv[t] = gp[t] * RSQ; cst.bpv[t] = bp[t];
    }
    __syncthreads();

    const int pt = tid >> 4;          // 0..7
    const int l  = tid & 15;
    const int i0 = blockIdx.x * 8 + pt;
    const int i  = (i0 < N) ? i0 : 0;   // clamp; final store guarded

    float* rvp = rv_s + pt * RV_PT_STRIDE;

    // ---- prep (lane = neighbor l): nj in register + pe hidden -> pad ----
    const int nj = idx[i * 16 + l];
    {
        float4 pc = g_p4[i];
        float4 pn = g_p4[nj];
        float prx = pn.x - pc.x, pry = pn.y - pc.y, prz = pn.z - pc.z;
        float u0 = cst.bp1v[0] + prx * cst.wp1[0] + pry * cst.wp1[3] + prz * cst.wp1[6];
        float u1 = cst.bp1v[1] + prx * cst.wp1[1] + pry * cst.wp1[4] + prz * cst.wp1[7];
        float u2 = cst.bp1v[2] + prx * cst.wp1[2] + pry * cst.wp1[5] + prz * cst.wp1[8];
        float h0 = fmaxf(fmaf(u0, cst.spv[0], cst.bpv[0]), 0.f);
        float h1 = fmaxf(fmaf(u1, cst.spv[1], cst.bpv[1]), 0.f);
        float h2 = fmaxf(fmaf(u2, cst.spv[2], cst.bpv[2]), 0.f);
        *(float4*)(rvp + l * RV_J_STRIDE + 32) = make_float4(h0, h1, h2, 0.f);
    }
    __syncwarp();

    float2 a2[4];
#pragma unroll
    for (int q = 0; q < 4; q++) a2[q] = *(const float2*)(cst.ba + q * 2);

    // ---- chunked stage + phase A (2 chunks of 32 channels) ----
#pragma unroll
    for (int cb = 0; cb < 64; cb += 32) {
        // stage: lane owns channels (cb+2l, cb+2l+1)
        const int c0 = cb + l * 2;
        float2 s12 = *(const float2*)(cst.s1 + c0);
        float2 xq2;
        {
            float2 q2 = *(const float2*)(g_q + (size_t)i * 64 + c0);
            float2 b2v = *(const float2*)(cst.bb1 + c0);
            xq2.x = fmaf(-q2.x, s12.x, b2v.x);
            xq2.y = fmaf(-q2.y, s12.y, b2v.y);
        }
        float2 w02 = *(const float2*)(cst.ws0 + c0);
        float2 w12 = *(const float2*)(cst.ws1 + c0);
        float2 w22 = *(const float2*)(cst.ws2 + c0);
        float2 wb2 = *(const float2*)(cst.wsb + c0);

#pragma unroll 4
        for (int jj = 0; jj < 16; jj++) {
            int    nb = __shfl_sync(0xffffffffu, nj, jj, 16);        // reg -> LDG addr
            float2 kv = *(const float2*)(g_k + (size_t)nb * 64 + c0);
            float4 h4 = *(const float4*)(rvp + jj * RV_J_STRIDE + 32); // bcast LDS
            float2 pe = fma2(make_float2(h4.x, h4.x), w02,
                        fma2(make_float2(h4.y, h4.y), w12,
                        fma2(make_float2(h4.z, h4.z), w22, wb2)));
            float2 arg = fma2(kv, s12, add2(xq2, pe));
            *(float2*)(rvp + jj * RV_J_STRIDE + l * 2) =
                make_float2(fmaxf(arg.x, 0.f), fmaxf(arg.y, 0.f));
        }
        __syncwarp();

        // phase A partial: lane = neighbor l; channels cb..cb+31
        {
            const float* rvj = rvp + l * RV_J_STRIDE;
#pragma unroll
            for (int c4 = 0; c4 < 8; c4++) {
                float4 rv4 = *(const float4*)(rvj + c4 * 4);
                float rvv[4] = {rv4.x, rv4.y, rv4.z, rv4.w};
#pragma unroll
                for (int ii = 0; ii < 4; ii++) {
                    const float* war = cst.wa + (cb + c4 * 4 + ii) * 8;
                    float4 wa0 = *(const float4*)(war);
                    float4 wa1 = *(const float4*)(war + 4);
                    float2 rr = make_float2(rvv[ii], rvv[ii]);
                    a2[0] = fma2(rr, make_float2(wa0.x, wa0.y), a2[0]);
                    a2[1] = fma2(rr, make_float2(wa0.z, wa0.w), a2[1]);
                    a2[2] = fma2(rr, make_float2(wa1.x, wa1.y), a2[2]);
                    a2[3] = fma2(rr, make_float2(wa1.z, wa1.w), a2[3]);
                }
            }
        }
        __syncwarp();
    }

    // ---- second MLP (8 -> 8) ----
    float2 b2[4];
#pragma unroll
    for (int q = 0; q < 4; q++) b2[q] = *(const float2*)(cst.bw + q * 2);
#pragma unroll
    for (int m = 0; m < 8; m++) {
        float avm = (m & 1) ? a2[m >> 1].y : a2[m >> 1].x;
        float t = fmaxf(fmaf(avm, cst.s2[m], cst.bb2[m]), 0.f);
        float2 tt = make_float2(t, t);
        const float2* wr = (const float2*)(cst.wbm + m * 8);
        b2[0] = fma2(tt, wr[0], b2[0]);
        b2[1] = fma2(tt, wr[1], b2[1]);
        b2[2] = fma2(tt, wr[2], b2[2]);
        b2[3] = fma2(tt, wr[3], b2[3]);
    }

    // ---- softmax over 16 neighbors, in place in b2 ----
    {
#pragma unroll
        for (int q = 0; q < 4; q++) {
            float2 v2 = b2[q];
            float mx0 = v2.x, mx1 = v2.y;
#pragma unroll
            for (int off = 8; off >= 1; off >>= 1) {
                mx0 = fmaxf(mx0, __shfl_xor_sync(0xffffffffu, mx0, off));
                mx1 = fmaxf(mx1, __shfl_xor_sync(0xffffffffu, mx1, off));
            }
            float e0 = __expf(v2.x - mx0);
            float e1 = __expf(v2.y - mx1);
            float s0 = e0, s1 = e1;
#pragma unroll
            for (int off = 8; off >= 1; off >>= 1) {
                s0 += __shfl_xor_sync(0xffffffffu, s0, off);
                s1 += __shfl_xor_sync(0xffffffffu, s1, off);
            }
            b2[q] = make_float2(__fdividef(e0, s0), __fdividef(e1, s1));
        }
    }
    // overlay softmax weights into dead rv words 12l..12l+7 (disjoint from h-pack)
    {
        float* wp = rvp + l * W_J_STRIDE;
        *(float4*)(wp)     = make_float4(b2[0].x, b2[0].y, b2[1].x, b2[1].y);
        *(float4*)(wp + 4) = make_float4(b2[2].x, b2[2].y, b2[3].x, b2[3].y);
    }
    __syncwarp();

    // ---- phase B: channel-parallel aggregation (coalesced v gather) ----
    const int c0 = l * 4;
    const int m0 = (l & 1) * 4;
    float4 rr0 = *(const float4*)(cst.r0 + c0);
    float4 rr1 = *(const float4*)(cst.r1 + c0);
    float4 rr2 = *(const float4*)(cst.r2 + c0);
    float4 rrb = *(const float4*)(cst.rb + c0);
    float2 acc01 = make_float2(0.f, 0.f), acc23 = make_float2(0.f, 0.f);
#pragma unroll 4
    for (int jj = 0; jj < 16; jj++) {
        int    nb = __shfl_sync(0xffffffffu, nj, jj, 16);          // reg -> LDG addr
        float4 v4 = *(const float4*)(g_v + (size_t)nb * 64 + c0);
        float4 h4 = *(const float4*)(rvp + jj * RV_J_STRIDE + 32); // bcast LDS
        float4 wv = *(const float4*)(rvp + jj * W_J_STRIDE + m0);
        float2 pe01 = fma2(make_float2(h4.x, h4.x), make_float2(rr0.x, rr0.y),
                      fma2(make_float2(h4.y, h4.y), make_float2(rr1.x, rr1.y),
                      fma2(make_float2(h4.z, h4.z), make_float2(rr2.x, rr2.y),
                           make_float2(rrb.x, rrb.y))));
        float2 pe23 = fma2(make_float2(h4.x, h4.x), make_float2(rr0.z, rr0.w),
                      fma2(make_float2(h4.y, h4.y), make_float2(rr1.z, rr1.w),
                      fma2(make_float2(h4.z, h4.z), make_float2(rr2.z, rr2.w),
                           make_float2(rrb.z, rrb.w))));
        acc01 = fma2(add2(make_float2(v4.x, v4.y), pe01), make_float2(wv.x, wv.y), acc01);
        acc23 = fma2(add2(make_float2(v4.z, v4.w), pe23), make_float2(wv.z, wv.w), acc23);
    }
    if (i0 < N)
        *(float4*)(outp + (size_t)i0 * 64 + c0) =
            make_float4(acc01.x, acc01.y, acc23.x, acc23.y);
}

// ============================================================================
extern "C" void kernel_launch(void* const* d_in, const int* in_sizes, int n_in,
                              void* d_out, int out_size) {
    const float* p   = (const float*)d_in[0];
    const float* x   = (const float*)d_in[1];
    const int*   idx = (const int*)d_in[2];
    const float* Wq  = (const float*)d_in[3];  const float* bq  = (const float*)d_in[4];
    const float* Wk  = (const float*)d_in[5];  const float* bk  = (const float*)d_in[6];
    const float* Wv  = (const float*)d_in[7];  const float* bv  = (const float*)d_in[8];
    const float* Wp1 = (const float*)d_in[9];  const float* bp1 = (const float*)d_in[10];
    const float* gp  = (const float*)d_in[11]; const float* bp  = (const float*)d_in[12];
    const float* Wp2 = (const float*)d_in[13]; const float* bp2 = (const float*)d_in[14];
    const float* g1  = (const float*)d_in[15]; const float* bb1 = (const float*)d_in[16];
    const float* Wa  = (const float*)d_in[17]; const float* ba  = (const float*)d_in[18];
    const float* g2  = (const float*)d_in[19]; const float* bb2 = (const float*)d_in[20];
    const float* Wb  = (const float*)d_in[21]; const float* bw  = (const float*)d_in[22];

    int N = in_sizes[0] / 3;
    if (N > MAXN) N = MAXN;  // scratch bound (problem shape is N=100000)

    const int qkv_dyn  = (64 * XS_STRIDE + 64 * WS_STRIDE) * (int)sizeof(float); // 68608
    const int attn_dyn = 8 * RV_PT_STRIDE * (int)sizeof(float);                  // 18688
    cudaFuncSetAttribute(qkv_kernel,  cudaFuncAttributeMaxDynamicSharedMemorySize, qkv_dyn);
    cudaFuncSetAttribute(attn_kernel, cudaFuncAttributeMaxDynamicSharedMemorySize, attn_dyn);

    qkv_kernel<<<(N + 63) / 64, 256, qkv_dyn>>>(x, p, Wq, bq, Wk, bk, Wv, bv, N);

    attn_kernel<<<(N + 7) / 8, 128, attn_dyn>>>(idx, Wp1, bp1, gp, bp, Wp2, bp2,
                                                g1, bb1, Wa, ba, g2, bb2, Wb, bw,
                                                (float*)d_out, N);
}

// round 12
// speedup vs baseline: 1.2045x; 1.0094x over previous
#include <cuda_runtime.h>
#include <cstdint>
#include <cstddef>

#define MAXN 131072

// scratch (device globals: no allocation allowed)
__device__ float g_q[MAXN * 64];
__device__ float g_k[MAXN * 64];
__device__ float g_v[MAXN * 64];
__device__ float4 g_p4[MAXN];
__device__ float g_wt[64 * 192];   // fused tf32 weights: [k][m*64+c]

// ---- packed fp32x2 ops (sm_103a FFMA2 path) ----
__device__ __forceinline__ float2 fma2(float2 a, float2 b, float2 c) {
    float2 d;
    asm("fma.rn.f32x2 %0, %1, %2, %3;"
        : "=l"(*(unsigned long long*)&d)
        : "l"(*(unsigned long long*)&a),
          "l"(*(unsigned long long*)&b),
          "l"(*(unsigned long long*)&c));
    return d;
}
__device__ __forceinline__ float2 add2(float2 a, float2 b) {
    float2 d;
    asm("add.rn.f32x2 %0, %1, %2;"
        : "=l"(*(unsigned long long*)&d)
        : "l"(*(unsigned long long*)&a),
          "l"(*(unsigned long long*)&b));
    return d;
}

// ---- tf32 helpers ----
__device__ __forceinline__ float to_tf32(float f) {
    uint32_t u;
    asm("cvt.rna.tf32.f32 %0, %1;" : "=r"(u) : "f"(f));
    return __uint_as_float(u);
}
__device__ __forceinline__ void mma_tf32(float4& d, const uint32_t* a,
                                         uint32_t b0, uint32_t b1) {
    asm volatile(
        "mma.sync.aligned.m16n8k8.row.col.f32.tf32.tf32.f32 "
        "{%0,%1,%2,%3}, {%4,%5,%6,%7}, {%8,%9}, {%0,%1,%2,%3};"
        : "+f"(d.x), "+f"(d.y), "+f"(d.z), "+f"(d.w)
        : "r"(a[0]), "r"(a[1]), "r"(a[2]), "r"(a[3]), "r"(b0), "r"(b1));
}

// ============================================================================
// Kernel 0: one-time fused weight pre-conversion to tf32 -> g_wt[k][m*64+c]
// ============================================================================
__global__ __launch_bounds__(256) void wconv_kernel(
    const float* __restrict__ Wq, const float* __restrict__ Wk,
    const float* __restrict__ Wv)
{
    int e = blockIdx.x * 256 + threadIdx.x;     // e < 12288
    if (e < 12288) {
        int m = e >> 12;            // 0..2
        int kc = e & 4095;
        int k = kc >> 6, c = kc & 63;
        const float* Wm = (m == 0) ? Wq : (m == 1) ? Wk : Wv;
        g_wt[k * 192 + m * 64 + c] = to_tf32(Wm[k * 64 + c]);
    }
}

// ============================================================================
// Kernel 1: fused q/k/v = x @ [Wq|Wk|Wv] + b via tf32 HMMA, p -> g_p4 repack.
// 64-row x 192-col tile per 256-thread block; weights pre-converted (g_wt).
// Epilogue staged through smem (ws region, dead after mainloop) for
// coalesced 4-sector STG.128 output stores.
// ============================================================================
#define XS_STRIDE 68
#define WS_STRIDE 200

__global__ __launch_bounds__(256) void qkv_kernel(
    const float* __restrict__ x, const float* __restrict__ p,
    const float* __restrict__ bq, const float* __restrict__ bk,
    const float* __restrict__ bv, int N)
{
    extern __shared__ float smem[];
    float* xs = smem;                         // 64 * 68 floats (tf32 values)
    float* ws = smem + 64 * XS_STRIDE;        // 64 * 200 floats
    const int tid = threadIdx.x;
    const int rowBase = blockIdx.x * 64;

    // fused pre-converted weights: g_wt packed [k][192] -> ws stride 200
    {
        const float4* src = (const float4*)g_wt;
        for (int e = tid; e < 3072; e += 256) {
            int k = e / 48, f = e % 48;
            *(float4*)(ws + k * WS_STRIDE + f * 4) = src[e];
        }
    }
    // x tile (tf32-converted, zero-pad past N)
    for (int e = tid; e < 1024; e += 256) {
        int r = e >> 4, c4 = e & 15;
        float4 v = make_float4(0.f, 0.f, 0.f, 0.f);
        if (rowBase + r < N) {
            v = *(const float4*)(x + (size_t)(rowBase + r) * 64 + c4 * 4);
            v.x = to_tf32(v.x); v.y = to_tf32(v.y);
            v.z = to_tf32(v.z); v.w = to_tf32(v.w);
        }
        *(float4*)(xs + r * XS_STRIDE + c4 * 4) = v;
    }
    // p repack (rows of this tile)
    if (tid < 64) {
        int row = rowBase + tid;
        if (row < N)
            g_p4[row] = make_float4(p[row * 3], p[row * 3 + 1], p[row * 3 + 2], 0.f);
    }
    __syncthreads();

    const int lane  = tid & 31;
    const int warp  = tid >> 5;
    const int rbase = (warp & 1) * 32;        // 2 row groups of 32
    const int cwb   = (warp >> 1) * 48;       // 4 col groups of 48 (6 n8 tiles)
    const int qd    = lane >> 2;              // 0..7
    const int cl    = lane & 3;               // 0..3

    // C frags, bias-initialized: .x/.z -> col g, .y/.w -> col g+1
    const float* bias[3] = {bq, bk, bv};
    float4 C[2][6];
#pragma unroll
    for (int rt = 0; rt < 2; rt++)
#pragma unroll
        for (int t = 0; t < 6; t++) {
            int g = cwb + t * 8 + 2 * cl;
            float b0v = bias[g >> 6][g & 63];
            float b1v = bias[g >> 6][(g & 63) + 1];
            C[rt][t] = make_float4(b0v, b1v, b0v, b1v);
        }

#pragma unroll
    for (int ks = 0; ks < 8; ks++) {
        const int k0 = ks * 8;
        uint32_t a[2][4];
#pragma unroll
        for (int rt = 0; rt < 2; rt++) {
            int r = rbase + rt * 16 + qd;
            a[rt][0] = __float_as_uint(xs[r * XS_STRIDE + k0 + cl]);
            a[rt][1] = __float_as_uint(xs[(r + 8) * XS_STRIDE + k0 + cl]);
            a[rt][2] = __float_as_uint(xs[r * XS_STRIDE + k0 + cl + 4]);
            a[rt][3] = __float_as_uint(xs[(r + 8) * XS_STRIDE + k0 + cl + 4]);
        }
#pragma unroll
        for (int t = 0; t < 6; t++) {
            int n0 = cwb + t * 8;
            uint32_t b0 = __float_as_uint(ws[(k0 + cl) * WS_STRIDE + n0 + qd]);
            uint32_t b1 = __float_as_uint(ws[(k0 + cl + 4) * WS_STRIDE + n0 + qd]);
            mma_tf32(C[0][t], a[0], b0, b1);
            mma_tf32(C[1][t], a[1], b0, b1);
        }
    }

    // ---- epilogue: frags -> smem (ws reused) -> coalesced STG.128 ----
    __syncthreads();   // everyone done reading ws (B frags)
#pragma unroll
    for (int rt = 0; rt < 2; rt++) {
        int lr0 = rbase + rt * 16 + qd;
#pragma unroll
        for (int t = 0; t < 6; t++) {
            int g = cwb + t * 8 + 2 * cl;
            *(float2*)(ws + lr0 * WS_STRIDE + g)       = make_float2(C[rt][t].x, C[rt][t].y);
            *(float2*)(ws + (lr0 + 8) * WS_STRIDE + g) = make_float2(C[rt][t].z, C[rt][t].w);
        }
    }
    __syncthreads();

    float* outs[3] = {g_q, g_k, g_v};
#pragma unroll
    for (int m = 0; m < 3; m++) {
        for (int e = tid; e < 1024; e += 256) {
            int r = e >> 4, c4 = e & 15;
            if (rowBase + r < N)
                *(float4*)(outs[m] + (size_t)(rowBase + r) * 64 + c4 * 4) =
                    *(const float4*)(ws + r * WS_STRIDE + m * 64 + c4 * 4);
        }
    }
}

// ============================================================================
// Kernel 2: fused attention (unchanged from R7 — protected win).
// ============================================================================
struct __align__(16) K2C {
    float s1[64], bb1[64];
    float ws0[64], ws1[64], ws2[64], wsb[64];  // s1-scaled Wp2 rows + s1*bp2
    float r0[64], r1[64], r2[64], rb[64];      // raw Wp2 rows + bp2 (phase B)
    float wa[512];                             // Wa [64][8] (rows 32B-aligned)
    float wbm[64];                             // Wb [8][8]
    float s2[8], bb2[8], ba[8], bw[8];
    float wp1[9], bp1v[3], spv[3], bpv[3];
};

#define RV_J_STRIDE 36          // 32 ch + 4 pad (pad holds h-pack)
#define RV_PT_STRIDE 584        // 16*36 + 8 stagger; % 32 == 8
#define W_J_STRIDE 12           // softmax weight row (8 + 4 gap), 48B

__global__ __launch_bounds__(128, 8) void attn_kernel(
    const int* __restrict__ idx,
    const float* __restrict__ Wp1, const float* __restrict__ bp1,
    const float* __restrict__ gp,  const float* __restrict__ bp,
    const float* __restrict__ Wp2, const float* __restrict__ bp2,
    const float* __restrict__ g1,  const float* __restrict__ bb1,
    const float* __restrict__ Wa,  const float* __restrict__ ba,
    const float* __restrict__ g2,  const float* __restrict__ bb2,
    const float* __restrict__ Wb,  const float* __restrict__ bw,
    float* __restrict__ outp, int N)
{
    __shared__ K2C cst;
    extern __shared__ __align__(16) float rv_s[];  // 8 * RV_PT_STRIDE floats

    const int tid = threadIdx.x;
    const float RSQ = rsqrtf(1.f + 1e-5f);

    // ---- constant prep ----
    if (tid < 64) {
        float s1v = g1[tid] * RSQ;
        cst.s1[tid]  = s1v;
        cst.bb1[tid] = bb1[tid];
        float w0 = Wp2[tid], w1 = Wp2[64 + tid], w2 = Wp2[128 + tid], bb = bp2[tid];
        cst.r0[tid] = w0;        cst.r1[tid] = w1;
        cst.r2[tid] = w2;        cst.rb[tid] = bb;
        cst.ws0[tid] = w0 * s1v; cst.ws1[tid] = w1 * s1v;
        cst.ws2[tid] = w2 * s1v; cst.wsb[tid] = bb * s1v;
        cst.wbm[tid] = Wb[tid];
    }
    for (int e = tid; e < 512; e += 128) cst.wa[e] = Wa[e];
    if (tid < 8) {
        cst.s2[tid] = g2[tid] * RSQ;
        cst.bb2[tid] = bb2[tid];
        cst.ba[tid]  = ba[tid];
        cst.bw[tid]  = bw[tid];
    }
    if (tid >= 64 && tid < 73) cst.wp1[tid - 64] = Wp1[tid - 64];
    if (tid >= 80 && tid < 83) {
        int t = tid - 80;
        cst.bp1v[t] = bp1[t]; cst.spv[t] = gp[t] * RSQ; cst.bpv[t] = bp[t];
    }
    __syncthreads();

    const int pt = tid >> 4;          // 0..7
    const int l  = tid & 15;
    const int i0 = blockIdx.x * 8 + pt;
    const int i  = (i0 < N) ? i0 : 0;   // clamp; final store guarded

    float* rvp = rv_s + pt * RV_PT_STRIDE;

    // ---- prep (lane = neighbor l): nj in register + pe hidden -> pad ----
    const int nj = idx[i * 16 + l];
    {
        float4 pc = g_p4[i];
        float4 pn = g_p4[nj];
        float prx = pn.x - pc.x, pry = pn.y - pc.y, prz = pn.z - pc.z;
        float u0 = cst.bp1v[0] + prx * cst.wp1[0] + pry * cst.wp1[3] + prz * cst.wp1[6];
        float u1 = cst.bp1v[1] + prx * cst.wp1[1] + pry * cst.wp1[4] + prz * cst.wp1[7];
        float u2 = cst.bp1v[2] + prx * cst.wp1[2] + pry * cst.wp1[5] + prz * cst.wp1[8];
        float h0 = fmaxf(fmaf(u0, cst.spv[0], cst.bpv[0]), 0.f);
        float h1 = fmaxf(fmaf(u1, cst.spv[1], cst.bpv[1]), 0.f);
        float h2 = fmaxf(fmaf(u2, cst.spv[2], cst.bpv[2]), 0.f);
        *(float4*)(rvp + l * RV_J_STRIDE + 32) = make_float4(h0, h1, h2, 0.f);
    }
    __syncwarp();

    float2 a2[4];
#pragma unroll
    for (int q = 0; q < 4; q++) a2[q] = *(const float2*)(cst.ba + q * 2);

    // ---- chunked stage + phase A (2 chunks of 32 channels) ----
#pragma unroll
    for (int cb = 0; cb < 64; cb += 32) {
        // stage: lane owns channels (cb+2l, cb+2l+1)
        const int c0 = cb + l * 2;
        float2 s12 = *(const float2*)(cst.s1 + c0);
        float2 xq2;
        {
            float2 q2 = *(const float2*)(g_q + (size_t)i * 64 + c0);
            float2 b2v = *(const float2*)(cst.bb1 + c0);
            xq2.x = fmaf(-q2.x, s12.x, b2v.x);
            xq2.y = fmaf(-q2.y, s12.y, b2v.y);
        }
        float2 w02 = *(const float2*)(cst.ws0 + c0);
        float2 w12 = *(const float2*)(cst.ws1 + c0);
        float2 w22 = *(const float2*)(cst.ws2 + c0);
        float2 wb2 = *(const float2*)(cst.wsb + c0);

#pragma unroll 4
        for (int jj = 0; jj < 16; jj++) {
            int    nb = __shfl_sync(0xffffffffu, nj, jj, 16);        // reg -> LDG addr
            float2 kv = *(const float2*)(g_k + (size_t)nb * 64 + c0);
            float4 h4 = *(const float4*)(rvp + jj * RV_J_STRIDE + 32); // bcast LDS
            float2 pe = fma2(make_float2(h4.x, h4.x), w02,
                        fma2(make_float2(h4.y, h4.y), w12,
                        fma2(make_float2(h4.z, h4.z), w22, wb2)));
            float2 arg = fma2(kv, s12, add2(xq2, pe));
            *(float2*)(rvp + jj * RV_J_STRIDE + l * 2) =
                make_float2(fmaxf(arg.x, 0.f), fmaxf(arg.y, 0.f));
        }
        __syncwarp();

        // phase A partial: lane = neighbor l; channels cb..cb+31
        {
            const float* rvj = rvp + l * RV_J_STRIDE;
#pragma unroll
            for (int c4 = 0; c4 < 8; c4++) {
                float4 rv4 = *(const float4*)(rvj + c4 * 4);
                float rvv[4] = {rv4.x, rv4.y, rv4.z, rv4.w};
#pragma unroll
                for (int ii = 0; ii < 4; ii++) {
                    const float* war = cst.wa + (cb + c4 * 4 + ii) * 8;
                    float4 wa0 = *(const float4*)(war);
                    float4 wa1 = *(const float4*)(war + 4);
                    float2 rr = make_float2(rvv[ii], rvv[ii]);
                    a2[0] = fma2(rr, make_float2(wa0.x, wa0.y), a2[0]);
                    a2[1] = fma2(rr, make_float2(wa0.z, wa0.w), a2[1]);
                    a2[2] = fma2(rr, make_float2(wa1.x, wa1.y), a2[2]);
                    a2[3] = fma2(rr, make_float2(wa1.z, wa1.w), a2[3]);
                }
            }
        }
        __syncwarp();
    }

    // ---- second MLP (8 -> 8) ----
    float2 b2[4];
#pragma unroll
    for (int q = 0; q < 4; q++) b2[q] = *(const float2*)(cst.bw + q * 2);
#pragma unroll
    for (int m = 0; m < 8; m++) {
        float avm = (m & 1) ? a2[m >> 1].y : a2[m >> 1].x;
        float t = fmaxf(fmaf(avm, cst.s2[m], cst.bb2[m]), 0.f);
        float2 tt = make_float2(t, t);
        const float2* wr = (const float2*)(cst.wbm + m * 8);
        b2[0] = fma2(tt, wr[0], b2[0]);
        b2[1] = fma2(tt, wr[1], b2[1]);
        b2[2] = fma2(tt, wr[2], b2[2]);
        b2[3] = fma2(tt, wr[3], b2[3]);
    }

    // ---- softmax over 16 neighbors, in place in b2 ----
    {
#pragma unroll
        for (int q = 0; q < 4; q++) {
            float2 v2 = b2[q];
            float mx0 = v2.x, mx1 = v2.y;
#pragma unroll
            for (int off = 8; off >= 1; off >>= 1) {
                mx0 = fmaxf(mx0, __shfl_xor_sync(0xffffffffu, mx0, off));
                mx1 = fmaxf(mx1, __shfl_xor_sync(0xffffffffu, mx1, off));
            }
            float e0 = __expf(v2.x - mx0);
            float e1 = __expf(v2.y - mx1);
            float s0 = e0, s1 = e1;
#pragma unroll
            for (int off = 8; off >= 1; off >>= 1) {
                s0 += __shfl_xor_sync(0xffffffffu, s0, off);
                s1 += __shfl_xor_sync(0xffffffffu, s1, off);
            }
            b2[q] = make_float2(__fdividef(e0, s0), __fdividef(e1, s1));
        }
    }
    // overlay softmax weights into dead rv words 12l..12l+7 (disjoint from h-pack)
    {
        float* wp = rvp + l * W_J_STRIDE;
        *(float4*)(wp)     = make_float4(b2[0].x, b2[0].y, b2[1].x, b2[1].y);
        *(float4*)(wp + 4) = make_float4(b2[2].x, b2[2].y, b2[3].x, b2[3].y);
    }
    __syncwarp();

    // ---- phase B: channel-parallel aggregation (coalesced v gather) ----
    const int c0 = l * 4;
    const int m0 = (l & 1) * 4;
    float4 rr0 = *(const float4*)(cst.r0 + c0);
    float4 rr1 = *(const float4*)(cst.r1 + c0);
    float4 rr2 = *(const float4*)(cst.r2 + c0);
    float4 rrb = *(const float4*)(cst.rb + c0);
    float2 acc01 = make_float2(0.f, 0.f), acc23 = make_float2(0.f, 0.f);
#pragma unroll 4
    for (int jj = 0; jj < 16; jj++) {
        int    nb = __shfl_sync(0xffffffffu, nj, jj, 16);          // reg -> LDG addr
        float4 v4 = *(const float4*)(g_v + (size_t)nb * 64 + c0);
        float4 h4 = *(const float4*)(rvp + jj * RV_J_STRIDE + 32); // bcast LDS
        float4 wv = *(const float4*)(rvp + jj * W_J_STRIDE + m0);
        float2 pe01 = fma2(make_float2(h4.x, h4.x), make_float2(rr0.x, rr0.y),
                      fma2(make_float2(h4.y, h4.y), make_float2(rr1.x, rr1.y),
                      fma2(make_float2(h4.z, h4.z), make_float2(rr2.x, rr2.y),
                           make_float2(rrb.x, rrb.y))));
        float2 pe23 = fma2(make_float2(h4.x, h4.x), make_float2(rr0.z, rr0.w),
                      fma2(make_float2(h4.y, h4.y), make_float2(rr1.z, rr1.w),
                      fma2(make_float2(h4.z, h4.z), make_float2(rr2.z, rr2.w),
                           make_float2(rrb.z, rrb.w))));
        acc01 = fma2(add2(make_float2(v4.x, v4.y), pe01), make_float2(wv.x, wv.y), acc01);
        acc23 = fma2(add2(make_float2(v4.z, v4.w), pe23), make_float2(wv.z, wv.w), acc23);
    }
    if (i0 < N)
        *(float4*)(outp + (size_t)i0 * 64 + c0) =
            make_float4(acc01.x, acc01.y, acc23.x, acc23.y);
}

// ============================================================================
extern "C" void kernel_launch(void* const* d_in, const int* in_sizes, int n_in,
                              void* d_out, int out_size) {
    const float* p   = (const float*)d_in[0];
    const float* x   = (const float*)d_in[1];
    const int*   idx = (const int*)d_in[2];
    const float* Wq  = (const float*)d_in[3];  const float* bq  = (const float*)d_in[4];
    const float* Wk  = (const float*)d_in[5];  const float* bk  = (const float*)d_in[6];
    const float* Wv  = (const float*)d_in[7];  const float* bv  = (const float*)d_in[8];
    const float* Wp1 = (const float*)d_in[9];  const float* bp1 = (const float*)d_in[10];
    const float* gp  = (const float*)d_in[11]; const float* bp  = (const float*)d_in[12];
    const float* Wp2 = (const float*)d_in[13]; const float* bp2 = (const float*)d_in[14];
    const float* g1  = (const float*)d_in[15]; const float* bb1 = (const float*)d_in[16];
    const float* Wa  = (const float*)d_in[17]; const float* ba  = (const float*)d_in[18];
    const float* g2  = (const float*)d_in[19]; const float* bb2 = (const float*)d_in[20];
    const float* Wb  = (const float*)d_in[21]; const float* bw  = (const float*)d_in[22];

    int N = in_sizes[0] / 3;
    if (N > MAXN) N = MAXN;  // scratch bound (problem shape is N=100000)

    const int qkv_dyn  = (64 * XS_STRIDE + 64 * WS_STRIDE) * (int)sizeof(float); // 68608
    const int attn_dyn = 8 * RV_PT_STRIDE * (int)sizeof(float);                  // 18688
    cudaFuncSetAttribute(qkv_kernel,  cudaFuncAttributeMaxDynamicSharedMemorySize, qkv_dyn);
    cudaFuncSetAttribute(attn_kernel, cudaFuncAttributeMaxDynamicSharedMemorySize, attn_dyn);

    wconv_kernel<<<48, 256>>>(Wq, Wk, Wv);

    qkv_kernel<<<(N + 63) / 64, 256, qkv_dyn>>>(x, p, bq, bk, bv, N);

    attn_kernel<<<(N + 7) / 8, 128, attn_dyn>>>(idx, Wp1, bp1, gp, bp, Wp2, bp2,
                                                g1, bb1, Wa, ba, g2, bb2, Wb, bw,
                                                (float*)d_out, N);
}

// round 13
// speedup vs baseline: 1.3345x; 1.1080x over previous
#include <cuda_runtime.h>
#include <cstdint>
#include <cstddef>

#define MAXN 131072

// scratch (device globals: no allocation allowed)
__device__ float g_q[MAXN * 64];
__device__ float g_k[MAXN * 64];
__device__ float g_v[MAXN * 64];
__device__ float4 g_p4[MAXN];
__device__ float g_wt[64 * 192];   // fused tf32 weights: [k][m*64+c]

// ---- packed fp32x2 ops (sm_103a FFMA2 path) ----
__device__ __forceinline__ float2 fma2(float2 a, float2 b, float2 c) {
    float2 d;
    asm("fma.rn.f32x2 %0, %1, %2, %3;"
        : "=l"(*(unsigned long long*)&d)
        : "l"(*(unsigned long long*)&a),
          "l"(*(unsigned long long*)&b),
          "l"(*(unsigned long long*)&c));
    return d;
}
__device__ __forceinline__ float2 add2(float2 a, float2 b) {
    float2 d;
    asm("add.rn.f32x2 %0, %1, %2;"
        : "=l"(*(unsigned long long*)&d)
        : "l"(*(unsigned long long*)&a),
          "l"(*(unsigned long long*)&b));
    return d;
}

// ---- tf32 helpers ----
__device__ __forceinline__ float to_tf32(float f) {
    uint32_t u;
    asm("cvt.rna.tf32.f32 %0, %1;" : "=r"(u) : "f"(f));
    return __uint_as_float(u);
}
__device__ __forceinline__ void mma_tf32(float4& d, const uint32_t* a,
                                         uint32_t b0, uint32_t b1) {
    asm volatile(
        "mma.sync.aligned.m16n8k8.row.col.f32.tf32.tf32.f32 "
        "{%0,%1,%2,%3}, {%4,%5,%6,%7}, {%8,%9}, {%0,%1,%2,%3};"
        : "+f"(d.x), "+f"(d.y), "+f"(d.z), "+f"(d.w)
        : "r"(a[0]), "r"(a[1]), "r"(a[2]), "r"(a[3]), "r"(b0), "r"(b1));
}

// ============================================================================
// Kernel 0: one-time fused weight pre-conversion to tf32 -> g_wt[k][m*64+c]
// ============================================================================
__global__ __launch_bounds__(256) void wconv_kernel(
    const float* __restrict__ Wq, const float* __restrict__ Wk,
    const float* __restrict__ Wv)
{
    int e = blockIdx.x * 256 + threadIdx.x;     // e < 12288
    if (e < 12288) {
        int m = e >> 12;            // 0..2
        int kc = e & 4095;
        int k = kc >> 6, c = kc & 63;
        const float* Wm = (m == 0) ? Wq : (m == 1) ? Wk : Wv;
        g_wt[k * 192 + m * 64 + c] = to_tf32(Wm[k * 64 + c]);
    }
}

// ============================================================================
// Kernel 1: fused q/k/v = x @ [Wq|Wk|Wv] + b via tf32 HMMA, p -> g_p4 repack.
// (unchanged from R11)
// ============================================================================
#define XS_STRIDE 68
#define WS_STRIDE 200

__global__ __launch_bounds__(256) void qkv_kernel(
    const float* __restrict__ x, const float* __restrict__ p,
    const float* __restrict__ bq, const float* __restrict__ bk,
    const float* __restrict__ bv, int N)
{
    extern __shared__ float smem[];
    float* xs = smem;                         // 64 * 68 floats (tf32 values)
    float* ws = smem + 64 * XS_STRIDE;        // 64 * 200 floats
    const int tid = threadIdx.x;
    const int rowBase = blockIdx.x * 64;

    // fused pre-converted weights: g_wt packed [k][192] -> ws stride 200
    {
        const float4* src = (const float4*)g_wt;
        for (int e = tid; e < 3072; e += 256) {
            int k = e / 48, f = e % 48;
            *(float4*)(ws + k * WS_STRIDE + f * 4) = src[e];
        }
    }
    // x tile (tf32-converted, zero-pad past N)
    for (int e = tid; e < 1024; e += 256) {
        int r = e >> 4, c4 = e & 15;
        float4 v = make_float4(0.f, 0.f, 0.f, 0.f);
        if (rowBase + r < N) {
            v = *(const float4*)(x + (size_t)(rowBase + r) * 64 + c4 * 4);
            v.x = to_tf32(v.x); v.y = to_tf32(v.y);
            v.z = to_tf32(v.z); v.w = to_tf32(v.w);
        }
        *(float4*)(xs + r * XS_STRIDE + c4 * 4) = v;
    }
    // p repack (rows of this tile)
    if (tid < 64) {
        int row = rowBase + tid;
        if (row < N)
            g_p4[row] = make_float4(p[row * 3], p[row * 3 + 1], p[row * 3 + 2], 0.f);
    }
    __syncthreads();

    const int lane  = tid & 31;
    const int warp  = tid >> 5;
    const int rbase = (warp & 1) * 32;        // 2 row groups of 32
    const int cwb   = (warp >> 1) * 48;       // 4 col groups of 48 (6 n8 tiles)
    const int qd    = lane >> 2;              // 0..7
    const int cl    = lane & 3;               // 0..3

    // C frags, bias-initialized: .x/.z -> col g, .y/.w -> col g+1
    const float* bias[3] = {bq, bk, bv};
    float4 C[2][6];
#pragma unroll
    for (int rt = 0; rt < 2; rt++)
#pragma unroll
        for (int t = 0; t < 6; t++) {
            int g = cwb + t * 8 + 2 * cl;
            float b0v = bias[g >> 6][g & 63];
            float b1v = bias[g >> 6][(g & 63) + 1];
            C[rt][t] = make_float4(b0v, b1v, b0v, b1v);
        }

#pragma unroll
    for (int ks = 0; ks < 8; ks++) {
        const int k0 = ks * 8;
        uint32_t a[2][4];
#pragma unroll
        for (int rt = 0; rt < 2; rt++) {
            int r = rbase + rt * 16 + qd;
            a[rt][0] = __float_as_uint(xs[r * XS_STRIDE + k0 + cl]);
            a[rt][1] = __float_as_uint(xs[(r + 8) * XS_STRIDE + k0 + cl]);
            a[rt][2] = __float_as_uint(xs[r * XS_STRIDE + k0 + cl + 4]);
            a[rt][3] = __float_as_uint(xs[(r + 8) * XS_STRIDE + k0 + cl + 4]);
        }
#pragma unroll
        for (int t = 0; t < 6; t++) {
            int n0 = cwb + t * 8;
            uint32_t b0 = __float_as_uint(ws[(k0 + cl) * WS_STRIDE + n0 + qd]);
            uint32_t b1 = __float_as_uint(ws[(k0 + cl + 4) * WS_STRIDE + n0 + qd]);
            mma_tf32(C[0][t], a[0], b0, b1);
            mma_tf32(C[1][t], a[1], b0, b1);
        }
    }

    // ---- epilogue: frags -> smem (ws reused) -> coalesced STG.128 ----
    __syncthreads();   // everyone done reading ws (B frags)
#pragma unroll
    for (int rt = 0; rt < 2; rt++) {
        int lr0 = rbase + rt * 16 + qd;
#pragma unroll
        for (int t = 0; t < 6; t++) {
            int g = cwb + t * 8 + 2 * cl;
            *(float2*)(ws + lr0 * WS_STRIDE + g)       = make_float2(C[rt][t].x, C[rt][t].y);
            *(float2*)(ws + (lr0 + 8) * WS_STRIDE + g) = make_float2(C[rt][t].z, C[rt][t].w);
        }
    }
    __syncthreads();

    float* outs[3] = {g_q, g_k, g_v};
#pragma unroll
    for (int m = 0; m < 3; m++) {
        for (int e = tid; e < 1024; e += 256) {
            int r = e >> 4, c4 = e & 15;
            if (rowBase + r < N)
                *(float4*)(outs[m] + (size_t)(rowBase + r) * 64 + c4 * 4) =
                    *(const float4*)(ws + r * WS_STRIDE + m * 64 + c4 * 4);
        }
    }
}

// ============================================================================
// Kernel 2: fused attention. Phase A (rv @ Wa) now runs on tensor cores:
// per point one m16n8 accumulator, k-chunked by 32 (4 mma k-steps per stage
// chunk) so smem layout / occupancy (8 blocks) are unchanged. rv and Wa are
// rna-rounded to tf32. BN2+ReLU applied in-fragment; a small STS/LDS
// round-trip through dead rv words 16..23 restores lane=neighbor layout so
// MLP2 / softmax / overlay / phase B are byte-for-byte the R7 code.
// ============================================================================
struct __align__(16) K2C {
    float s1[64], bb1[64];
    float ws0[64], ws1[64], ws2[64], wsb[64];  // s1-scaled Wp2 rows + s1*bp2
    float r0[64], r1[64], r2[64], rb[64];      // raw Wp2 rows + bp2 (phase B)
    float wa[512];                             // Wa [64][8], tf32-rounded
    float wbm[64];                             // Wb [8][8]
    float s2[8], bb2[8], ba[8], bw[8];
    float wp1[9], bp1v[3], spv[3], bpv[3];
};

#define RV_J_STRIDE 36          // 32 ch + 4 pad (pad holds h-pack)
#define RV_PT_STRIDE 584        // 16*36 + 8 stagger; % 32 == 8
#define W_J_STRIDE 12           // softmax weight row (8 + 4 gap), 48B

__global__ __launch_bounds__(128, 8) void attn_kernel(
    const int* __restrict__ idx,
    const float* __restrict__ Wp1, const float* __restrict__ bp1,
    const float* __restrict__ gp,  const float* __restrict__ bp,
    const float* __restrict__ Wp2, const float* __restrict__ bp2,
    const float* __restrict__ g1,  const float* __restrict__ bb1,
    const float* __restrict__ Wa,  const float* __restrict__ ba,
    const float* __restrict__ g2,  const float* __restrict__ bb2,
    const float* __restrict__ Wb,  const float* __restrict__ bw,
    float* __restrict__ outp, int N)
{
    __shared__ K2C cst;
    extern __shared__ __align__(16) float rv_s[];  // 8 * RV_PT_STRIDE floats

    const int tid = threadIdx.x;
    const float RSQ = rsqrtf(1.f + 1e-5f);

    // ---- constant prep ----
    if (tid < 64) {
        float s1v = g1[tid] * RSQ;
        cst.s1[tid]  = s1v;
        cst.bb1[tid] = bb1[tid];
        float w0 = Wp2[tid], w1 = Wp2[64 + tid], w2 = Wp2[128 + tid], bb = bp2[tid];
        cst.r0[tid] = w0;        cst.r1[tid] = w1;
        cst.r2[tid] = w2;        cst.rb[tid] = bb;
        cst.ws0[tid] = w0 * s1v; cst.ws1[tid] = w1 * s1v;
        cst.ws2[tid] = w2 * s1v; cst.wsb[tid] = bb * s1v;
        cst.wbm[tid] = Wb[tid];
    }
    for (int e = tid; e < 512; e += 128) cst.wa[e] = to_tf32(Wa[e]);
    if (tid < 8) {
        cst.s2[tid] = g2[tid] * RSQ;
        cst.bb2[tid] = bb2[tid];
        cst.ba[tid]  = ba[tid];
        cst.bw[tid]  = bw[tid];
    }
    if (tid >= 64 && tid < 73) cst.wp1[tid - 64] = Wp1[tid - 64];
    if (tid >= 80 && tid < 83) {
        int t = tid - 80;
        cst.bp1v[t] = bp1[t]; cst.spv[t] = gp[t] * RSQ; cst.bpv[t] = bp[t];
    }
    __syncthreads();

    const int pt   = tid >> 4;        // 0..7 (this lane's point)
    const int l    = tid & 15;
    const int lane = tid & 31;
    const int qd   = lane >> 2;       // mma frag row group
    const int cl   = lane & 3;        // mma frag col group
    const int wpt  = (tid >> 5) * 2;  // first point of this warp
    const int i0 = blockIdx.x * 8 + pt;
    const int i  = (i0 < N) ? i0 : 0;   // clamp; final store guarded

    float* rvp = rv_s + pt * RV_PT_STRIDE;

    // ---- prep (lane = neighbor l): nj in register + pe hidden -> pad ----
    const int nj = idx[i * 16 + l];
    {
        float4 pc = g_p4[i];
        float4 pn = g_p4[nj];
        float prx = pn.x - pc.x, pry = pn.y - pc.y, prz = pn.z - pc.z;
        float u0 = cst.bp1v[0] + prx * cst.wp1[0] + pry * cst.wp1[3] + prz * cst.wp1[6];
        float u1 = cst.bp1v[1] + prx * cst.wp1[1] + pry * cst.wp1[4] + prz * cst.wp1[7];
        float u2 = cst.bp1v[2] + prx * cst.wp1[2] + pry * cst.wp1[5] + prz * cst.wp1[8];
        float h0 = fmaxf(fmaf(u0, cst.spv[0], cst.bpv[0]), 0.f);
        float h1 = fmaxf(fmaf(u1, cst.spv[1], cst.bpv[1]), 0.f);
        float h2 = fmaxf(fmaf(u2, cst.spv[2], cst.bpv[2]), 0.f);
        *(float4*)(rvp + l * RV_J_STRIDE + 32) = make_float4(h0, h1, h2, 0.f);
    }
    __syncwarp();

    // mma accumulators (one 16x8 per point), bias-initialized
    float4 D[2];
    {
        float2 bav = *(const float2*)(cst.ba + 2 * cl);
        D[0] = make_float4(bav.x, bav.y, bav.x, bav.y);
        D[1] = D[0];
    }

    // ---- chunked stage + tensor-core phase A (2 chunks of 32 channels) ----
#pragma unroll
    for (int cb = 0; cb < 64; cb += 32) {
        // stage: lane owns channels (cb+2l, cb+2l+1); rv stored tf32-rounded
        const int c0 = cb + l * 2;
        float2 s12 = *(const float2*)(cst.s1 + c0);
        float2 xq2;
        {
            float2 q2 = *(const float2*)(g_q + (size_t)i * 64 + c0);
            float2 b2v = *(const float2*)(cst.bb1 + c0);
            xq2.x = fmaf(-q2.x, s12.x, b2v.x);
            xq2.y = fmaf(-q2.y, s12.y, b2v.y);
        }
        float2 w02 = *(const float2*)(cst.ws0 + c0);
        float2 w12 = *(const float2*)(cst.ws1 + c0);
        float2 w22 = *(const float2*)(cst.ws2 + c0);
        float2 wb2 = *(const float2*)(cst.wsb + c0);

#pragma unroll 4
        for (int jj = 0; jj < 16; jj++) {
            int    nb = __shfl_sync(0xffffffffu, nj, jj, 16);        // reg -> LDG addr
            float2 kv = *(const float2*)(g_k + (size_t)nb * 64 + c0);
            float4 h4 = *(const float4*)(rvp + jj * RV_J_STRIDE + 32); // bcast LDS
            float2 pe = fma2(make_float2(h4.x, h4.x), w02,
                        fma2(make_float2(h4.y, h4.y), w12,
                        fma2(make_float2(h4.z, h4.z), w22, wb2)));
            float2 arg = fma2(kv, s12, add2(xq2, pe));
            *(float2*)(rvp + jj * RV_J_STRIDE + l * 2) =
                make_float2(to_tf32(fmaxf(arg.x, 0.f)),
                            to_tf32(fmaxf(arg.y, 0.f)));
        }
        __syncwarp();

        // phase A partial on tensor cores: D[o] += rv_chunk @ Wa[cb..cb+31]
#pragma unroll
        for (int ks = 0; ks < 4; ks++) {
            const int k0 = ks * 8;
            uint32_t b0 = __float_as_uint(cst.wa[(cb + k0 + cl) * 8 + qd]);
            uint32_t b1 = __float_as_uint(cst.wa[(cb + k0 + cl + 4) * 8 + qd]);
#pragma unroll
            for (int o = 0; o < 2; o++) {
                const float* rq = rv_s + (wpt + o) * RV_PT_STRIDE;
                uint32_t a[4];
                a[0] = __float_as_uint(rq[qd * RV_J_STRIDE + k0 + cl]);
                a[1] = __float_as_uint(rq[(qd + 8) * RV_J_STRIDE + k0 + cl]);
                a[2] = __float_as_uint(rq[qd * RV_J_STRIDE + k0 + cl + 4]);
                a[3] = __float_as_uint(rq[(qd + 8) * RV_J_STRIDE + k0 + cl + 4]);
                mma_tf32(D[o], a, b0, b1);
            }
        }
        __syncwarp();   // mma reads done before next chunk overwrites rv
    }

    // ---- BN2 + ReLU in-fragment, stash t into dead rv words 16..23 ----
    {
        float2 s2v  = *(const float2*)(cst.s2  + 2 * cl);
        float2 bb2v = *(const float2*)(cst.bb2 + 2 * cl);
#pragma unroll
        for (int o = 0; o < 2; o++) {
            float* rq = rv_s + (wpt + o) * RV_PT_STRIDE;
            float t0 = fmaxf(fmaf(D[o].x, s2v.x, bb2v.x), 0.f);
            float t1 = fmaxf(fmaf(D[o].y, s2v.y, bb2v.y), 0.f);
            float t2 = fmaxf(fmaf(D[o].z, s2v.x, bb2v.x), 0.f);
            float t3 = fmaxf(fmaf(D[o].w, s2v.y, bb2v.y), 0.f);
            *(float2*)(rq + qd * RV_J_STRIDE + 16 + 2 * cl)       = make_float2(t0, t1);
            *(float2*)(rq + (qd + 8) * RV_J_STRIDE + 16 + 2 * cl) = make_float2(t2, t3);
        }
    }
    __syncwarp();

    // restore lane=neighbor layout: lane l reads its own t row
    float2 a2[4];
    {
        float4 ta = *(const float4*)(rvp + l * RV_J_STRIDE + 16);
        float4 tb = *(const float4*)(rvp + l * RV_J_STRIDE + 20);
        a2[0] = make_float2(ta.x, ta.y);
        a2[1] = make_float2(ta.z, ta.w);
        a2[2] = make_float2(tb.x, tb.y);
        a2[3] = make_float2(tb.z, tb.w);
    }

    // ---- second MLP (8 -> 8); BN2+ReLU already applied ----
    float2 b2[4];
#pragma unroll
    for (int q = 0; q < 4; q++) b2[q] = *(const float2*)(cst.bw + q * 2);
#pragma unroll
    for (int m = 0; m < 8; m++) {
        float t = (m & 1) ? a2[m >> 1].y : a2[m >> 1].x;
        float2 tt = make_float2(t, t);
        const float2* wr = (const float2*)(cst.wbm + m * 8);
        b2[0] = fma2(tt, wr[0], b2[0]);
        b2[1] = fma2(tt, wr[1], b2[1]);
        b2[2] = fma2(tt, wr[2], b2[2]);
        b2[3] = fma2(tt, wr[3], b2[3]);
    }

    // ---- softmax over 16 neighbors, in place in b2 ----
    {
#pragma unroll
        for (int q = 0; q < 4; q++) {
            float2 v2 = b2[q];
            float mx0 = v2.x, mx1 = v2.y;
#pragma unroll
            for (int off = 8; off >= 1; off >>= 1) {
                mx0 = fmaxf(mx0, __shfl_xor_sync(0xffffffffu, mx0, off));
                mx1 = fmaxf(mx1, __shfl_xor_sync(0xffffffffu, mx1, off));
            }
            float e0 = __expf(v2.x - mx0);
            float e1 = __expf(v2.y - mx1);
            float s0 = e0, s1 = e1;
#pragma unroll
            for (int off = 8; off >= 1; off >>= 1) {
                s0 += __shfl_xor_sync(0xffffffffu, s0, off);
                s1 += __shfl_xor_sync(0xffffffffu, s1, off);
            }
            b2[q] = make_float2(__fdividef(e0, s0), __fdividef(e1, s1));
        }
    }
    // overlay softmax weights into dead rv words 12l..12l+7 (disjoint from h-pack)
    {
        float* wp = rvp + l * W_J_STRIDE;
        *(float4*)(wp)     = make_float4(b2[0].x, b2[0].y, b2[1].x, b2[1].y);
        *(float4*)(wp + 4) = make_float4(b2[2].x, b2[2].y, b2[3].x, b2[3].y);
    }
    __syncwarp();

    // ---- phase B: channel-parallel aggregation (coalesced v gather) ----
    const int c0 = l * 4;
    const int m0 = (l & 1) * 4;
    float4 rr0 = *(const float4*)(cst.r0 + c0);
    float4 rr1 = *(const float4*)(cst.r1 + c0);
    float4 rr2 = *(const float4*)(cst.r2 + c0);
    float4 rrb = *(const float4*)(cst.rb + c0);
    float2 acc01 = make_float2(0.f, 0.f), acc23 = make_float2(0.f, 0.f);
#pragma unroll 4
    for (int jj = 0; jj < 16; jj++) {
        int    nb = __shfl_sync(0xffffffffu, nj, jj, 16);          // reg -> LDG addr
        float4 v4 = *(const float4*)(g_v + (size_t)nb * 64 + c0);
        float4 h4 = *(const float4*)(rvp + jj * RV_J_STRIDE + 32); // bcast LDS
        float4 wv = *(const float4*)(rvp + jj * W_J_STRIDE + m0);
        float2 pe01 = fma2(make_float2(h4.x, h4.x), make_float2(rr0.x, rr0.y),
                      fma2(make_float2(h4.y, h4.y), make_float2(rr1.x, rr1.y),
                      fma2(make_float2(h4.z, h4.z), make_float2(rr2.x, rr2.y),
                           make_float2(rrb.x, rrb.y))));
        float2 pe23 = fma2(make_float2(h4.x, h4.x), make_float2(rr0.z, rr0.w),
                      fma2(make_float2(h4.y, h4.y), make_float2(rr1.z, rr1.w),
                      fma2(make_float2(h4.z, h4.z), make_float2(rr2.z, rr2.w),
                           make_float2(rrb.z, rrb.w))));
        acc01 = fma2(add2(make_float2(v4.x, v4.y), pe01), make_float2(wv.x, wv.y), acc01);
        acc23 = fma2(add2(make_float2(v4.z, v4.w), pe23), make_float2(wv.z, wv.w), acc23);
    }
    if (i0 < N)
        *(float4*)(outp + (size_t)i0 * 64 + c0) =
            make_float4(acc01.x, acc01.y, acc23.x, acc23.y);
}

// ============================================================================
extern "C" void kernel_launch(void* const* d_in, const int* in_sizes, int n_in,
                              void* d_out, int out_size) {
    const float* p   = (const float*)d_in[0];
    const float* x   = (const float*)d_in[1];
    const int*   idx = (const int*)d_in[2];
    const float* Wq  = (const float*)d_in[3];  const float* bq  = (const float*)d_in[4];
    const float* Wk  = (const float*)d_in[5];  const float* bk  = (const float*)d_in[6];
    const float* Wv  = (const float*)d_in[7];  const float* bv  = (const float*)d_in[8];
    const float* Wp1 = (const float*)d_in[9];  const float* bp1 = (const float*)d_in[10];
    const float* gp  = (const float*)d_in[11]; const float* bp  = (const float*)d_in[12];
    const float* Wp2 = (const float*)d_in[13]; const float* bp2 = (const float*)d_in[14];
    const float* g1  = (const float*)d_in[15]; const float* bb1 = (const float*)d_in[16];
    const float* Wa  = (const float*)d_in[17]; const float* ba  = (const float*)d_in[18];
    const float* g2  = (const float*)d_in[19]; const float* bb2 = (const float*)d_in[20];
    const float* Wb  = (const float*)d_in[21]; const float* bw  = (const float*)d_in[22];

    int N = in_sizes[0] / 3;
    if (N > MAXN) N = MAXN;  // scratch bound (problem shape is N=100000)

    const int qkv_dyn  = (64 * XS_STRIDE + 64 * WS_STRIDE) * (int)sizeof(float); // 68608
    const int attn_dyn = 8 * RV_PT_STRIDE * (int)sizeof(float);                  // 18688
    cudaFuncSetAttribute(qkv_kernel,  cudaFuncAttributeMaxDynamicSharedMemorySize, qkv_dyn);
    cudaFuncSetAttribute(attn_kernel, cudaFuncAttributeMaxDynamicSharedMemorySize, attn_dyn);

    wconv_kernel<<<48, 256>>>(Wq, Wk, Wv);

    qkv_kernel<<<(N + 63) / 64, 256, qkv_dyn>>>(x, p, bq, bk, bv, N);

    attn_kernel<<<(N + 7) / 8, 128, attn_dyn>>>(idx, Wp1, bp1, gp, bp, Wp2, bp2,
                                                g1, bb1, Wa, ba, g2, bb2, Wb, bw,
                                                (float*)d_out, N);
}

// round 14
// speedup vs baseline: 1.4532x; 1.0889x over previous
#include <cuda_runtime.h>
#include <cstdint>
#include <cstddef>

#define MAXN 131072

// scratch (device globals: no allocation allowed)
__device__ float g_q[MAXN * 64];
__device__ float g_k[MAXN * 64];
__device__ float g_v[MAXN * 64];
__device__ float4 g_p4[MAXN];
__device__ float g_wt[64 * 192];   // fused tf32 weights: [k][m*64+c]

// ---- packed fp32x2 ops (sm_103a FFMA2 path) ----
__device__ __forceinline__ float2 fma2(float2 a, float2 b, float2 c) {
    float2 d;
    asm("fma.rn.f32x2 %0, %1, %2, %3;"
        : "=l"(*(unsigned long long*)&d)
        : "l"(*(unsigned long long*)&a),
          "l"(*(unsigned long long*)&b),
          "l"(*(unsigned long long*)&c));
    return d;
}
__device__ __forceinline__ float2 add2(float2 a, float2 b) {
    float2 d;
    asm("add.rn.f32x2 %0, %1, %2;"
        : "=l"(*(unsigned long long*)&d)
        : "l"(*(unsigned long long*)&a),
          "l"(*(unsigned long long*)&b));
    return d;
}

// ---- tf32 helpers ----
__device__ __forceinline__ float to_tf32(float f) {
    uint32_t u;
    asm("cvt.rna.tf32.f32 %0, %1;" : "=r"(u) : "f"(f));
    return __uint_as_float(u);
}
__device__ __forceinline__ void mma_tf32(float4& d, const uint32_t* a,
                                         uint32_t b0, uint32_t b1) {
    asm volatile(
        "mma.sync.aligned.m16n8k8.row.col.f32.tf32.tf32.f32 "
        "{%0,%1,%2,%3}, {%4,%5,%6,%7}, {%8,%9}, {%0,%1,%2,%3};"
        : "+f"(d.x), "+f"(d.y), "+f"(d.z), "+f"(d.w)
        : "r"(a[0]), "r"(a[1]), "r"(a[2]), "r"(a[3]), "r"(b0), "r"(b1));
}
__device__ __forceinline__ void cp_async16(void* smem_dst, const void* gmem_src) {
    uint32_t s = (uint32_t)__cvta_generic_to_shared(smem_dst);
    asm volatile("cp.async.cg.shared.global [%0], [%1], 16;"
                 :: "r"(s), "l"(gmem_src) : "memory");
}
__device__ __forceinline__ void cp_commit() {
    asm volatile("cp.async.commit_group;" ::: "memory");
}
__device__ __forceinline__ void cp_wait0() {
    asm volatile("cp.async.wait_group 0;" ::: "memory");
}

// ============================================================================
// Kernel 0: one-time fused weight pre-conversion to tf32 -> g_wt[k][m*64+c]
// ============================================================================
__global__ __launch_bounds__(256) void wconv_kernel(
    const float* __restrict__ Wq, const float* __restrict__ Wk,
    const float* __restrict__ Wv)
{
    int e = blockIdx.x * 256 + threadIdx.x;     // e < 12288
    if (e < 12288) {
        int m = e >> 12;            // 0..2
        int kc = e & 4095;
        int k = kc >> 6, c = kc & 63;
        const float* Wm = (m == 0) ? Wq : (m == 1) ? Wk : Wv;
        g_wt[k * 192 + m * 64 + c] = to_tf32(Wm[k * 64 + c]);
    }
}

// ============================================================================
// Kernel 1: PERSISTENT fused q/k/v via tf32 HMMA + p -> g_p4 repack.
// 304 blocks grid-stride over 64-row tiles. Weights loaded to smem ONCE per
// block. x tiles double-buffered via cp.async (prefetch next tile during
// mainloop). x consumed as raw fp32 bits (tf32 truncation); weights are
// rna-rounded (g_wt). Epilogue staged per-matrix through the just-freed x
// buffer (stride 68, 16B-aligned) for coalesced STG.128.
// ============================================================================
#define XS_STRIDE 68
#define WS_STRIDE 200
#define QKV_GRID 304

__global__ __launch_bounds__(256, 2) void qkv_kernel(
    const float* __restrict__ x, const float* __restrict__ p,
    const float* __restrict__ bq, const float* __restrict__ bk,
    const float* __restrict__ bv, int N, int numTiles)
{
    extern __shared__ float smem[];
    float* ws   = smem;                          // 64*200 = 51200B
    float* buf0 = smem + 64 * WS_STRIDE;         // 64*68  = 17408B
    float* buf1 = buf0 + 64 * XS_STRIDE;         // 64*68  = 17408B
    const int tid = threadIdx.x;

    // ---- weights once per block ----
    {
        const float4* src = (const float4*)g_wt;
        for (int e = tid; e < 3072; e += 256) {
            int k = e / 48, f = e % 48;
            *(float4*)(ws + k * WS_STRIDE + f * 4) = src[e];
        }
    }

    const int lane  = tid & 31;
    const int warp  = tid >> 5;
    const int rbase = (warp & 1) * 32;
    const int cwb   = (warp >> 1) * 48;
    const int qd    = lane >> 2;
    const int cl    = lane & 3;

    // bias fragments hoisted (per-thread constants)
    const float* bias[3] = {bq, bk, bv};
    float bfr[6][2];
#pragma unroll
    for (int t6 = 0; t6 < 6; t6++) {
        int g = cwb + t6 * 8 + 2 * cl;
        bfr[t6][0] = bias[g >> 6][g & 63];
        bfr[t6][1] = bias[g >> 6][(g & 63) + 1];
    }

    float* bufs[2] = {buf0, buf1};

    // ---- prologue: prefetch first tile ----
    int t0 = blockIdx.x;
    if (t0 < numTiles) {
        int rowBase = t0 * 64;
        for (int e = tid; e < 1024; e += 256) {
            int r = e >> 4, c4 = e & 15;
            float* d = buf0 + r * XS_STRIDE + c4 * 4;
            int row = rowBase + r;
            if (row < N)
                cp_async16(d, x + (size_t)row * 64 + c4 * 4);
            else
                *(float4*)d = make_float4(0.f, 0.f, 0.f, 0.f);
        }
    }
    cp_commit();

    int cur = 0;
    for (int t = blockIdx.x; t < numTiles; t += QKV_GRID) {
        const int rowBase = t * 64;
        cp_wait0();
        __syncthreads();          // buf[cur] ready; ws visible; prev staging done

        // prefetch next tile into the other buffer
        {
            int tn = t + QKV_GRID;
            if (tn < numTiles) {
                int rb2 = tn * 64;
                float* dst = bufs[cur ^ 1];
                for (int e = tid; e < 1024; e += 256) {
                    int r = e >> 4, c4 = e & 15;
                    float* d = dst + r * XS_STRIDE + c4 * 4;
                    int row = rb2 + r;
                    if (row < N)
                        cp_async16(d, x + (size_t)row * 64 + c4 * 4);
                    else
                        *(float4*)d = make_float4(0.f, 0.f, 0.f, 0.f);
                }
            }
            cp_commit();
        }
        // p repack for this tile (independent of barriers)
        if (tid < 64) {
            int row = rowBase + tid;
            if (row < N)
                g_p4[row] = make_float4(p[row * 3], p[row * 3 + 1],
                                        p[row * 3 + 2], 0.f);
        }

        float* xs = bufs[cur];

        // ---- mainloop ----
        float4 C[2][6];
#pragma unroll
        for (int rt = 0; rt < 2; rt++)
#pragma unroll
            for (int t6 = 0; t6 < 6; t6++)
                C[rt][t6] = make_float4(bfr[t6][0], bfr[t6][1],
                                        bfr[t6][0], bfr[t6][1]);

#pragma unroll
        for (int ks = 0; ks < 8; ks++) {
            const int k0 = ks * 8;
            uint32_t a[2][4];
#pragma unroll
            for (int rt = 0; rt < 2; rt++) {
                int r = rbase + rt * 16 + qd;
                a[rt][0] = __float_as_uint(xs[r * XS_STRIDE + k0 + cl]);
                a[rt][1] = __float_as_uint(xs[(r + 8) * XS_STRIDE + k0 + cl]);
                a[rt][2] = __float_as_uint(xs[r * XS_STRIDE + k0 + cl + 4]);
                a[rt][3] = __float_as_uint(xs[(r + 8) * XS_STRIDE + k0 + cl + 4]);
            }
#pragma unroll
            for (int t6 = 0; t6 < 6; t6++) {
                int n0 = cwb + t6 * 8;
                uint32_t b0 = __float_as_uint(ws[(k0 + cl) * WS_STRIDE + n0 + qd]);
                uint32_t b1 = __float_as_uint(ws[(k0 + cl + 4) * WS_STRIDE + n0 + qd]);
                mma_tf32(C[0][t6], a[0], b0, b1);
                mma_tf32(C[1][t6], a[1], b0, b1);
            }
        }
        __syncthreads();          // xs dead -> reuse as staging

        // ---- epilogue: 3 matrices staged through xs ----
        float* outs[3] = {g_q, g_k, g_v};
        float* stg = xs;
#pragma unroll
        for (int m = 0; m < 3; m++) {
#pragma unroll
            for (int t6 = 0; t6 < 6; t6++) {
                if (((cwb + 8 * t6) >> 6) == m) {
                    int cc = (cwb + 8 * t6 + 2 * cl) & 63;
#pragma unroll
                    for (int rt = 0; rt < 2; rt++) {
                        int lr0 = rbase + rt * 16 + qd;
                        *(float2*)(stg + lr0 * XS_STRIDE + cc) =
                            make_float2(C[rt][t6].x, C[rt][t6].y);
                        *(float2*)(stg + (lr0 + 8) * XS_STRIDE + cc) =
                            make_float2(C[rt][t6].z, C[rt][t6].w);
                    }
                }
            }
            __syncthreads();
            float* outm = outs[m];
            for (int e = tid; e < 1024; e += 256) {
                int r = e >> 4, c4 = e & 15;
                int row = rowBase + r;
                if (row < N)
                    *(float4*)(outm + (size_t)row * 64 + c4 * 4) =
                        *(const float4*)(stg + r * XS_STRIDE + c4 * 4);
            }
            __syncthreads();
        }
        cur ^= 1;
    }
}

// ============================================================================
// Kernel 2: fused attention (unchanged from R12 — protected win).
// ============================================================================
struct __align__(16) K2C {
    float s1[64], bb1[64];
    float ws0[64], ws1[64], ws2[64], wsb[64];  // s1-scaled Wp2 rows + s1*bp2
    float r0[64], r1[64], r2[64], rb[64];      // raw Wp2 rows + bp2 (phase B)
    float wa[512];                             // Wa [64][8], tf32-rounded
    float wbm[64];                             // Wb [8][8]
    float s2[8], bb2[8], ba[8], bw[8];
    float wp1[9], bp1v[3], spv[3], bpv[3];
};

#define RV_J_STRIDE 36          // 32 ch + 4 pad (pad holds h-pack)
#define RV_PT_STRIDE 584        // 16*36 + 8 stagger; % 32 == 8
#define W_J_STRIDE 12           // softmax weight row (8 + 4 gap), 48B

__global__ __launch_bounds__(128, 8) void attn_kernel(
    const int* __restrict__ idx,
    const float* __restrict__ Wp1, const float* __restrict__ bp1,
    const float* __restrict__ gp,  const float* __restrict__ bp,
    const float* __restrict__ Wp2, const float* __restrict__ bp2,
    const float* __restrict__ g1,  const float* __restrict__ bb1,
    const float* __restrict__ Wa,  const float* __restrict__ ba,
    const float* __restrict__ g2,  const float* __restrict__ bb2,
    const float* __restrict__ Wb,  const float* __restrict__ bw,
    float* __restrict__ outp, int N)
{
    __shared__ K2C cst;
    extern __shared__ __align__(16) float rv_s[];  // 8 * RV_PT_STRIDE floats

    const int tid = threadIdx.x;
    const float RSQ = rsqrtf(1.f + 1e-5f);

    // ---- constant prep ----
    if (tid < 64) {
        float s1v = g1[tid] * RSQ;
        cst.s1[tid]  = s1v;
        cst.bb1[tid] = bb1[tid];
        float w0 = Wp2[tid], w1 = Wp2[64 + tid], w2 = Wp2[128 + tid], bb = bp2[tid];
        cst.r0[tid] = w0;        cst.r1[tid] = w1;
        cst.r2[tid] = w2;        cst.rb[tid] = bb;
        cst.ws0[tid] = w0 * s1v; cst.ws1[tid] = w1 * s1v;
        cst.ws2[tid] = w2 * s1v; cst.wsb[tid] = bb * s1v;
        cst.wbm[tid] = Wb[tid];
    }
    for (int e = tid; e < 512; e += 128) cst.wa[e] = to_tf32(Wa[e]);
    if (tid < 8) {
        cst.s2[tid] = g2[tid] * RSQ;
        cst.bb2[tid] = bb2[tid];
        cst.ba[tid]  = ba[tid];
        cst.bw[tid]  = bw[tid];
    }
    if (tid >= 64 && tid < 73) cst.wp1[tid - 64] = Wp1[tid - 64];
    if (tid >= 80 && tid < 83) {
        int t = tid - 80;
        cst.bp1v[t] = bp1[t]; cst.spv[t] = gp[t] * RSQ; cst.bpv[t] = bp[t];
    }
    __syncthreads();

    const int pt   = tid >> 4;        // 0..7 (this lane's point)
    const int l    = tid & 15;
    const int lane = tid & 31;
    const int qd   = lane >> 2;       // mma frag row group
    const int cl   = lane & 3;        // mma frag col group
    const int wpt  = (tid >> 5) * 2;  // first point of this warp
    const int i0 = blockIdx.x * 8 + pt;
    const int i  = (i0 < N) ? i0 : 0;   // clamp; final store guarded

    float* rvp = rv_s + pt * RV_PT_STRIDE;

    // ---- prep (lane = neighbor l): nj in register + pe hidden -> pad ----
    const int nj = idx[i * 16 + l];
    {
        float4 pc = g_p4[i];
        float4 pn = g_p4[nj];
        float prx = pn.x - pc.x, pry = pn.y - pc.y, prz = pn.z - pc.z;
        float u0 = cst.bp1v[0] + prx * cst.wp1[0] + pry * cst.wp1[3] + prz * cst.wp1[6];
        float u1 = cst.bp1v[1] + prx * cst.wp1[1] + pry * cst.wp1[4] + prz * cst.wp1[7];
        float u2 = cst.bp1v[2] + prx * cst.wp1[2] + pry * cst.wp1[5] + prz * cst.wp1[8];
        float h0 = fmaxf(fmaf(u0, cst.spv[0], cst.bpv[0]), 0.f);
        float h1 = fmaxf(fmaf(u1, cst.spv[1], cst.bpv[1]), 0.f);
        float h2 = fmaxf(fmaf(u2, cst.spv[2], cst.bpv[2]), 0.f);
        *(float4*)(rvp + l * RV_J_STRIDE + 32) = make_float4(h0, h1, h2, 0.f);
    }
    __syncwarp();

    // mma accumulators (one 16x8 per point), bias-initialized
    float4 D[2];
    {
        float2 bav = *(const float2*)(cst.ba + 2 * cl);
        D[0] = make_float4(bav.x, bav.y, bav.x, bav.y);
        D[1] = D[0];
    }

    // ---- chunked stage + tensor-core phase A (2 chunks of 32 channels) ----
#pragma unroll
    for (int cb = 0; cb < 64; cb += 32) {
        // stage: lane owns channels (cb+2l, cb+2l+1); rv stored tf32-rounded
        const int c0 = cb + l * 2;
        float2 s12 = *(const float2*)(cst.s1 + c0);
        float2 xq2;
        {
            float2 q2 = *(const float2*)(g_q + (size_t)i * 64 + c0);
            float2 b2v = *(const float2*)(cst.bb1 + c0);
            xq2.x = fmaf(-q2.x, s12.x, b2v.x);
            xq2.y = fmaf(-q2.y, s12.y, b2v.y);
        }
        float2 w02 = *(const float2*)(cst.ws0 + c0);
        float2 w12 = *(const float2*)(cst.ws1 + c0);
        float2 w22 = *(const float2*)(cst.ws2 + c0);
        float2 wb2 = *(const float2*)(cst.wsb + c0);

#pragma unroll 4
        for (int jj = 0; jj < 16; jj++) {
            int    nb = __shfl_sync(0xffffffffu, nj, jj, 16);        // reg -> LDG addr
            float2 kv = *(const float2*)(g_k + (size_t)nb * 64 + c0);
            float4 h4 = *(const float4*)(rvp + jj * RV_J_STRIDE + 32); // bcast LDS
            float2 pe = fma2(make_float2(h4.x, h4.x), w02,
                        fma2(make_float2(h4.y, h4.y), w12,
                        fma2(make_float2(h4.z, h4.z), w22, wb2)));
            float2 arg = fma2(kv, s12, add2(xq2, pe));
            *(float2*)(rvp + jj * RV_J_STRIDE + l * 2) =
                make_float2(to_tf32(fmaxf(arg.x, 0.f)),
                            to_tf32(fmaxf(arg.y, 0.f)));
        }
        __syncwarp();

        // phase A partial on tensor cores: D[o] += rv_chunk @ Wa[cb..cb+31]
#pragma unroll
        for (int ks = 0; ks < 4; ks++) {
            const int k0 = ks * 8;
            uint32_t b0 = __float_as_uint(cst.wa[(cb + k0 + cl) * 8 + qd]);
            uint32_t b1 = __float_as_uint(cst.wa[(cb + k0 + cl + 4) * 8 + qd]);
#pragma unroll
            for (int o = 0; o < 2; o++) {
                const float* rq = rv_s + (wpt + o) * RV_PT_STRIDE;
                uint32_t a[4];
                a[0] = __float_as_uint(rq[qd * RV_J_STRIDE + k0 + cl]);
                a[1] = __float_as_uint(rq[(qd + 8) * RV_J_STRIDE + k0 + cl]);
                a[2] = __float_as_uint(rq[qd * RV_J_STRIDE + k0 + cl + 4]);
                a[3] = __float_as_uint(rq[(qd + 8) * RV_J_STRIDE + k0 + cl + 4]);
                mma_tf32(D[o], a, b0, b1);
            }
        }
        __syncwarp();   // mma reads done before next chunk overwrites rv
    }

    // ---- BN2 + ReLU in-fragment, stash t into dead rv words 16..23 ----
    {
        float2 s2v  = *(const float2*)(cst.s2  + 2 * cl);
        float2 bb2v = *(const float2*)(cst.bb2 + 2 * cl);
#pragma unroll
        for (int o = 0; o < 2; o++) {
            float* rq = rv_s + (wpt + o) * RV_PT_STRIDE;
            float t0 = fmaxf(fmaf(D[o].x, s2v.x, bb2v.x), 0.f);
            float t1 = fmaxf(fmaf(D[o].y, s2v.y, bb2v.y), 0.f);
            float t2 = fmaxf(fmaf(D[o].z, s2v.x, bb2v.x), 0.f);
            float t3 = fmaxf(fmaf(D[o].w, s2v.y, bb2v.y), 0.f);
            *(float2*)(rq + qd * RV_J_STRIDE + 16 + 2 * cl)       = make_float2(t0, t1);
            *(float2*)(rq + (qd + 8) * RV_J_STRIDE + 16 + 2 * cl) = make_float2(t2, t3);
        }
    }
    __syncwarp();

    // restore lane=neighbor layout: lane l reads its own t row
    float2 a2[4];
    {
        float4 ta = *(const float4*)(rvp + l * RV_J_STRIDE + 16);
        float4 tb = *(const float4*)(rvp + l * RV_J_STRIDE + 20);
        a2[0] = make_float2(ta.x, ta.y);
        a2[1] = make_float2(ta.z, ta.w);
        a2[2] = make_float2(tb.x, tb.y);
        a2[3] = make_float2(tb.z, tb.w);
    }

    // ---- second MLP (8 -> 8); BN2+ReLU already applied ----
    float2 b2[4];
#pragma unroll
    for (int q = 0; q < 4; q++) b2[q] = *(const float2*)(cst.bw + q * 2);
#pragma unroll
    for (int m = 0; m < 8; m++) {
        float t = (m & 1) ? a2[m >> 1].y : a2[m >> 1].x;
        float2 tt = make_float2(t, t);
        const float2* wr = (const float2*)(cst.wbm + m * 8);
        b2[0] = fma2(tt, wr[0], b2[0]);
        b2[1] = fma2(tt, wr[1], b2[1]);
        b2[2] = fma2(tt, wr[2], b2[2]);
        b2[3] = fma2(tt, wr[3], b2[3]);
    }

    // ---- softmax over 16 neighbors, in place in b2 ----
    {
#pragma unroll
        for (int q = 0; q < 4; q++) {
            float2 v2 = b2[q];
            float mx0 = v2.x, mx1 = v2.y;
#pragma unroll
            for (int off = 8; off >= 1; off >>= 1) {
                mx0 = fmaxf(mx0, __shfl_xor_sync(0xffffffffu, mx0, off));
                mx1 = fmaxf(mx1, __shfl_xor_sync(0xffffffffu, mx1, off));
            }
            float e0 = __expf(v2.x - mx0);
            float e1 = __expf(v2.y - mx1);
            float s0 = e0, s1 = e1;
#pragma unroll
            for (int off = 8; off >= 1; off >>= 1) {
                s0 += __shfl_xor_sync(0xffffffffu, s0, off);
                s1 += __shfl_xor_sync(0xffffffffu, s1, off);
            }
            b2[q] = make_float2(__fdividef(e0, s0), __fdividef(e1, s1));
        }
    }
    // overlay softmax weights into dead rv words 12l..12l+7 (disjoint from h-pack)
    {
        float* wp = rvp + l * W_J_STRIDE;
        *(float4*)(wp)     = make_float4(b2[0].x, b2[0].y, b2[1].x, b2[1].y);
        *(float4*)(wp + 4) = make_float4(b2[2].x, b2[2].y, b2[3].x, b2[3].y);
    }
    __syncwarp();

    // ---- phase B: channel-parallel aggregation (coalesced v gather) ----
    const int c0 = l * 4;
    const int m0 = (l & 1) * 4;
    float4 rr0 = *(const float4*)(cst.r0 + c0);
    float4 rr1 = *(const float4*)(cst.r1 + c0);
    float4 rr2 = *(const float4*)(cst.r2 + c0);
    float4 rrb = *(const float4*)(cst.rb + c0);
    float2 acc01 = make_float2(0.f, 0.f), acc23 = make_float2(0.f, 0.f);
#pragma unroll 4
    for (int jj = 0; jj < 16; jj++) {
        int    nb = __shfl_sync(0xffffffffu, nj, jj, 16);          // reg -> LDG addr
        float4 v4 = *(const float4*)(g_v + (size_t)nb * 64 + c0);
        float4 h4 = *(const float4*)(rvp + jj * RV_J_STRIDE + 32); // bcast LDS
        float4 wv = *(const float4*)(rvp + jj * W_J_STRIDE + m0);
        float2 pe01 = fma2(make_float2(h4.x, h4.x), make_float2(rr0.x, rr0.y),
                      fma2(make_float2(h4.y, h4.y), make_float2(rr1.x, rr1.y),
                      fma2(make_float2(h4.z, h4.z), make_float2(rr2.x, rr2.y),
                           make_float2(rrb.x, rrb.y))));
        float2 pe23 = fma2(make_float2(h4.x, h4.x), make_float2(rr0.z, rr0.w),
                      fma2(make_float2(h4.y, h4.y), make_float2(rr1.z, rr1.w),
                      fma2(make_float2(h4.z, h4.z), make_float2(rr2.z, rr2.w),
                           make_float2(rrb.z, rrb.w))));
        acc01 = fma2(add2(make_float2(v4.x, v4.y), pe01), make_float2(wv.x, wv.y), acc01);
        acc23 = fma2(add2(make_float2(v4.z, v4.w), pe23), make_float2(wv.z, wv.w), acc23);
    }
    if (i0 < N)
        *(float4*)(outp + (size_t)i0 * 64 + c0) =
            make_float4(acc01.x, acc01.y, acc23.x, acc23.y);
}

// ============================================================================
extern "C" void kernel_launch(void* const* d_in, const int* in_sizes, int n_in,
                              void* d_out, int out_size) {
    const float* p   = (const float*)d_in[0];
    const float* x   = (const float*)d_in[1];
    const int*   idx = (const int*)d_in[2];
    const float* Wq  = (const float*)d_in[3];  const float* bq  = (const float*)d_in[4];
    const float* Wk  = (const float*)d_in[5];  const float* bk  = (const float*)d_in[6];
    const float* Wv  = (const float*)d_in[7];  const float* bv  = (const float*)d_in[8];
    const float* Wp1 = (const float*)d_in[9];  const float* bp1 = (const float*)d_in[10];
    const float* gp  = (const float*)d_in[11]; const float* bp  = (const float*)d_in[12];
    const float* Wp2 = (const float*)d_in[13]; const float* bp2 = (const float*)d_in[14];
    const float* g1  = (const float*)d_in[15]; const float* bb1 = (const float*)d_in[16];
    const float* Wa  = (const float*)d_in[17]; const float* ba  = (const float*)d_in[18];
    const float* g2  = (const float*)d_in[19]; const float* bb2 = (const float*)d_in[20];
    const float* Wb  = (const float*)d_in[21]; const float* bw  = (const float*)d_in[22];

    int N = in_sizes[0] / 3;
    if (N > MAXN) N = MAXN;  // scratch bound (problem shape is N=100000)
    int numTiles = (N + 63) / 64;

    const int qkv_dyn  = (64 * WS_STRIDE + 2 * 64 * XS_STRIDE) * (int)sizeof(float); // 86016
    const int attn_dyn = 8 * RV_PT_STRIDE * (int)sizeof(float);                      // 18688
    cudaFuncSetAttribute(qkv_kernel,  cudaFuncAttributeMaxDynamicSharedMemorySize, qkv_dyn);
    cudaFuncSetAttribute(attn_kernel, cudaFuncAttributeMaxDynamicSharedMemorySize, attn_dyn);

    wconv_kernel<<<48, 256>>>(Wq, Wk, Wv);

    qkv_kernel<<<QKV_GRID, 256, qkv_dyn>>>(x, p, bq, bk, bv, N, numTiles);

    attn_kernel<<<(N + 7) / 8, 128, attn_dyn>>>(idx, Wp1, bp1, gp, bp, Wp2, bp2,
                                                g1, bb1, Wa, ba, g2, bb2, Wb, bw,
                                                (float*)d_out, N);
}

// round 15
// speedup vs baseline: 1.5439x; 1.0625x over previous
#include <cuda_runtime.h>
#include <cuda_fp16.h>
#include <cstdint>
#include <cstddef>

#define MAXN 131072

// scratch (device globals: no allocation allowed)
__device__ float  g_q[MAXN * 64];
__device__ float  g_k[MAXN * 64];
__device__ __half g_hv[MAXN * 64];   // v stored fp16 (halves gather lines)
__device__ float4 g_p4[MAXN];

// ---- packed fp32x2 ops (sm_103a FFMA2 path) ----
__device__ __forceinline__ float2 fma2(float2 a, float2 b, float2 c) {
    float2 d;
    asm("fma.rn.f32x2 %0, %1, %2, %3;"
        : "=l"(*(unsigned long long*)&d)
        : "l"(*(unsigned long long*)&a),
          "l"(*(unsigned long long*)&b),
          "l"(*(unsigned long long*)&c));
    return d;
}
__device__ __forceinline__ float2 add2(float2 a, float2 b) {
    float2 d;
    asm("add.rn.f32x2 %0, %1, %2;"
        : "=l"(*(unsigned long long*)&d)
        : "l"(*(unsigned long long*)&a),
          "l"(*(unsigned long long*)&b));
    return d;
}

// ---- tf32 helpers ----
__device__ __forceinline__ float to_tf32(float f) {
    uint32_t u;
    asm("cvt.rna.tf32.f32 %0, %1;" : "=r"(u) : "f"(f));
    return __uint_as_float(u);
}
__device__ __forceinline__ void mma_tf32(float4& d, const uint32_t* a,
                                         uint32_t b0, uint32_t b1) {
    asm volatile(
        "mma.sync.aligned.m16n8k8.row.col.f32.tf32.tf32.f32 "
        "{%0,%1,%2,%3}, {%4,%5,%6,%7}, {%8,%9}, {%0,%1,%2,%3};"
        : "+f"(d.x), "+f"(d.y), "+f"(d.z), "+f"(d.w)
        : "r"(a[0]), "r"(a[1]), "r"(a[2]), "r"(a[3]), "r"(b0), "r"(b1));
}
__device__ __forceinline__ void cp_async16(void* smem_dst, const void* gmem_src) {
    uint32_t s = (uint32_t)__cvta_generic_to_shared(smem_dst);
    asm volatile("cp.async.cg.shared.global [%0], [%1], 16;"
                 :: "r"(s), "l"(gmem_src) : "memory");
}
__device__ __forceinline__ void cp_commit() {
    asm volatile("cp.async.commit_group;" ::: "memory");
}
__device__ __forceinline__ void cp_wait0() {
    asm volatile("cp.async.wait_group 0;" ::: "memory");
}

// ============================================================================
// Kernel 1: PERSISTENT fused q/k/v via tf32 HMMA + p -> g_p4 repack.
// 304 blocks grid-stride over 64-row tiles. Weights cvt'd+loaded ONCE per
// block (wconv kernel folded in). x double-buffered via cp.async. v output
// converted to fp16 in the epilogue.
// ============================================================================
#define XS_STRIDE 68
#define WS_STRIDE 200
#define QKV_GRID 304

__global__ __launch_bounds__(256, 2) void qkv_kernel(
    const float* __restrict__ x, const float* __restrict__ p,
    const float* __restrict__ Wq, const float* __restrict__ Wk,
    const float* __restrict__ Wv,
    const float* __restrict__ bq, const float* __restrict__ bk,
    const float* __restrict__ bv, int N, int numTiles)
{
    extern __shared__ float smem[];
    float* ws   = smem;                          // 64*200 = 51200B
    float* buf0 = smem + 64 * WS_STRIDE;         // 64*68  = 17408B
    float* buf1 = buf0 + 64 * XS_STRIDE;         // 64*68  = 17408B
    const int tid = threadIdx.x;

    // ---- weights once per block (cvt to tf32 here; wconv folded in) ----
    {
        const float* Wm[3] = {Wq, Wk, Wv};
#pragma unroll
        for (int m = 0; m < 3; m++) {
            const float4* src = (const float4*)Wm[m];
            for (int e = tid; e < 1024; e += 256) {
                int k = e >> 4, c4 = e & 15;
                float4 v = src[e];
                v.x = to_tf32(v.x); v.y = to_tf32(v.y);
                v.z = to_tf32(v.z); v.w = to_tf32(v.w);
                *(float4*)(ws + k * WS_STRIDE + m * 64 + c4 * 4) = v;
            }
        }
    }

    const int lane  = tid & 31;
    const int warp  = tid >> 5;
    const int rbase = (warp & 1) * 32;
    const int cwb   = (warp >> 1) * 48;
    const int qd    = lane >> 2;
    const int cl    = lane & 3;

    // bias fragments hoisted (per-thread constants)
    const float* bias[3] = {bq, bk, bv};
    float bfr[6][2];
#pragma unroll
    for (int t6 = 0; t6 < 6; t6++) {
        int g = cwb + t6 * 8 + 2 * cl;
        bfr[t6][0] = bias[g >> 6][g & 63];
        bfr[t6][1] = bias[g >> 6][(g & 63) + 1];
    }

    float* bufs[2] = {buf0, buf1};

    // ---- prologue: prefetch first tile ----
    int t0 = blockIdx.x;
    if (t0 < numTiles) {
        int rowBase = t0 * 64;
        for (int e = tid; e < 1024; e += 256) {
            int r = e >> 4, c4 = e & 15;
            float* d = buf0 + r * XS_STRIDE + c4 * 4;
            int row = rowBase + r;
            if (row < N)
                cp_async16(d, x + (size_t)row * 64 + c4 * 4);
            else
                *(float4*)d = make_float4(0.f, 0.f, 0.f, 0.f);
        }
    }
    cp_commit();

    int cur = 0;
    for (int t = blockIdx.x; t < numTiles; t += QKV_GRID) {
        const int rowBase = t * 64;
        cp_wait0();
        __syncthreads();          // buf[cur] ready; ws visible; prev staging done

        // prefetch next tile into the other buffer
        {
            int tn = t + QKV_GRID;
            if (tn < numTiles) {
                int rb2 = tn * 64;
                float* dst = bufs[cur ^ 1];
                for (int e = tid; e < 1024; e += 256) {
                    int r = e >> 4, c4 = e & 15;
                    float* d = dst + r * XS_STRIDE + c4 * 4;
                    int row = rb2 + r;
                    if (row < N)
                        cp_async16(d, x + (size_t)row * 64 + c4 * 4);
                    else
                        *(float4*)d = make_float4(0.f, 0.f, 0.f, 0.f);
                }
            }
            cp_commit();
        }
        // p repack for this tile (independent of barriers)
        if (tid < 64) {
            int row = rowBase + tid;
            if (row < N)
                g_p4[row] = make_float4(p[row * 3], p[row * 3 + 1],
                                        p[row * 3 + 2], 0.f);
        }

        float* xs = bufs[cur];

        // ---- mainloop ----
        float4 C[2][6];
#pragma unroll
        for (int rt = 0; rt < 2; rt++)
#pragma unroll
            for (int t6 = 0; t6 < 6; t6++)
                C[rt][t6] = make_float4(bfr[t6][0], bfr[t6][1],
                                        bfr[t6][0], bfr[t6][1]);

#pragma unroll
        for (int ks = 0; ks < 8; ks++) {
            const int k0 = ks * 8;
            uint32_t a[2][4];
#pragma unroll
            for (int rt = 0; rt < 2; rt++) {
                int r = rbase + rt * 16 + qd;
                a[rt][0] = __float_as_uint(xs[r * XS_STRIDE + k0 + cl]);
                a[rt][1] = __float_as_uint(xs[(r + 8) * XS_STRIDE + k0 + cl]);
                a[rt][2] = __float_as_uint(xs[r * XS_STRIDE + k0 + cl + 4]);
                a[rt][3] = __float_as_uint(xs[(r + 8) * XS_STRIDE + k0 + cl + 4]);
            }
#pragma unroll
            for (int t6 = 0; t6 < 6; t6++) {
                int n0 = cwb + t6 * 8;
                uint32_t b0 = __float_as_uint(ws[(k0 + cl) * WS_STRIDE + n0 + qd]);
                uint32_t b1 = __float_as_uint(ws[(k0 + cl + 4) * WS_STRIDE + n0 + qd]);
                mma_tf32(C[0][t6], a[0], b0, b1);
                mma_tf32(C[1][t6], a[1], b0, b1);
            }
        }
        __syncthreads();          // xs dead -> reuse as staging

        // ---- epilogue: 3 matrices staged through xs; v converted to fp16 ----
        float* stg = xs;
#pragma unroll
        for (int m = 0; m < 3; m++) {
#pragma unroll
            for (int t6 = 0; t6 < 6; t6++) {
                if (((cwb + 8 * t6) >> 6) == m) {
                    int cc = (cwb + 8 * t6 + 2 * cl) & 63;
#pragma unroll
                    for (int rt = 0; rt < 2; rt++) {
                        int lr0 = rbase + rt * 16 + qd;
                        *(float2*)(stg + lr0 * XS_STRIDE + cc) =
                            make_float2(C[rt][t6].x, C[rt][t6].y);
                        *(float2*)(stg + (lr0 + 8) * XS_STRIDE + cc) =
                            make_float2(C[rt][t6].z, C[rt][t6].w);
                    }
                }
            }
            __syncthreads();
            if (m < 2) {
                float* outm = (m == 0) ? g_q : g_k;
                for (int e = tid; e < 1024; e += 256) {
                    int r = e >> 4, c4 = e & 15;
                    int row = rowBase + r;
                    if (row < N)
                        *(float4*)(outm + (size_t)row * 64 + c4 * 4) =
                            *(const float4*)(stg + r * XS_STRIDE + c4 * 4);
                }
            } else {
                for (int e = tid; e < 1024; e += 256) {
                    int r = e >> 4, c4 = e & 15;
                    int row = rowBase + r;
                    if (row < N) {
                        float4 vv = *(const float4*)(stg + r * XS_STRIDE + c4 * 4);
                        __half2 h2[2];
                        h2[0] = __floats2half2_rn(vv.x, vv.y);
                        h2[1] = __floats2half2_rn(vv.z, vv.w);
                        *(uint2*)(g_hv + (size_t)row * 64 + c4 * 4) = *(uint2*)h2;
                    }
                }
            }
            __syncthreads();
        }
        cur ^= 1;
    }
}

// ============================================================================
// Kernel 2: fused attention. vs R13: (a) phase B v gathered as fp16 (half
// the lines), (b) softmax max-subtraction removed (logits are O(0.2);
// exp-ratio identity keeps results exact modulo overflow, impossible here).
// Everything else identical to the protected R12/R13 structure.
// ============================================================================
struct __align__(16) K2C {
    float s1[64], bb1[64];
    float ws0[64], ws1[64], ws2[64], wsb[64];  // s1-scaled Wp2 rows + s1*bp2
    float r0[64], r1[64], r2[64], rb[64];      // raw Wp2 rows + bp2 (phase B)
    float wa[512];                             // Wa [64][8], tf32-rounded
    float wbm[64];                             // Wb [8][8]
    float s2[8], bb2[8], ba[8], bw[8];
    float wp1[9], bp1v[3], spv[3], bpv[3];
};

#define RV_J_STRIDE 36          // 32 ch + 4 pad (pad holds h-pack)
#define RV_PT_STRIDE 584        // 16*36 + 8 stagger; % 32 == 8
#define W_J_STRIDE 12           // softmax weight row (8 + 4 gap), 48B

__global__ __launch_bounds__(128, 8) void attn_kernel(
    const int* __restrict__ idx,
    const float* __restrict__ Wp1, const float* __restrict__ bp1,
    const float* __restrict__ gp,  const float* __restrict__ bp,
    const float* __restrict__ Wp2, const float* __restrict__ bp2,
    const float* __restrict__ g1,  const float* __restrict__ bb1,
    const float* __restrict__ Wa,  const float* __restrict__ ba,
    const float* __restrict__ g2,  const float* __restrict__ bb2,
    const float* __restrict__ Wb,  const float* __restrict__ bw,
    float* __restrict__ outp, int N)
{
    __shared__ K2C cst;
    extern __shared__ __align__(16) float rv_s[];  // 8 * RV_PT_STRIDE floats

    const int tid = threadIdx.x;
    const float RSQ = rsqrtf(1.f + 1e-5f);

    // ---- constant prep ----
    if (tid < 64) {
        float s1v = g1[tid] * RSQ;
        cst.s1[tid]  = s1v;
        cst.bb1[tid] = bb1[tid];
        float w0 = Wp2[tid], w1 = Wp2[64 + tid], w2 = Wp2[128 + tid], bb = bp2[tid];
        cst.r0[tid] = w0;        cst.r1[tid] = w1;
        cst.r2[tid] = w2;        cst.rb[tid] = bb;
        cst.ws0[tid] = w0 * s1v; cst.ws1[tid] = w1 * s1v;
        cst.ws2[tid] = w2 * s1v; cst.wsb[tid] = bb * s1v;
        cst.wbm[tid] = Wb[tid];
    }
    for (int e = tid; e < 512; e += 128) cst.wa[e] = to_tf32(Wa[e]);
    if (tid < 8) {
        cst.s2[tid] = g2[tid] * RSQ;
        cst.bb2[tid] = bb2[tid];
        cst.ba[tid]  = ba[tid];
        cst.bw[tid]  = bw[tid];
    }
    if (tid >= 64 && tid < 73) cst.wp1[tid - 64] = Wp1[tid - 64];
    if (tid >= 80 && tid < 83) {
        int t = tid - 80;
        cst.bp1v[t] = bp1[t]; cst.spv[t] = gp[t] * RSQ; cst.bpv[t] = bp[t];
    }
    __syncthreads();

    const int pt   = tid >> 4;        // 0..7 (this lane's point)
    const int l    = tid & 15;
    const int lane = tid & 31;
    const int qd   = lane >> 2;       // mma frag row group
    const int cl   = lane & 3;        // mma frag col group
    const int wpt  = (tid >> 5) * 2;  // first point of this warp
    const int i0 = blockIdx.x * 8 + pt;
    const int i  = (i0 < N) ? i0 : 0;   // clamp; final store guarded

    float* rvp = rv_s + pt * RV_PT_STRIDE;

    // ---- prep (lane = neighbor l): nj in register + pe hidden -> pad ----
    const int nj = idx[i * 16 + l];
    {
        float4 pc = g_p4[i];
        float4 pn = g_p4[nj];
        float prx = pn.x - pc.x, pry = pn.y - pc.y, prz = pn.z - pc.z;
        float u0 = cst.bp1v[0] + prx * cst.wp1[0] + pry * cst.wp1[3] + prz * cst.wp1[6];
        float u1 = cst.bp1v[1] + prx * cst.wp1[1] + pry * cst.wp1[4] + prz * cst.wp1[7];
        float u2 = cst.bp1v[2] + prx * cst.wp1[2] + pry * cst.wp1[5] + prz * cst.wp1[8];
        float h0 = fmaxf(fmaf(u0, cst.spv[0], cst.bpv[0]), 0.f);
        float h1 = fmaxf(fmaf(u1, cst.spv[1], cst.bpv[1]), 0.f);
        float h2 = fmaxf(fmaf(u2, cst.spv[2], cst.bpv[2]), 0.f);
        *(float4*)(rvp + l * RV_J_STRIDE + 32) = make_float4(h0, h1, h2, 0.f);
    }
    __syncwarp();

    // mma accumulators (one 16x8 per point), bias-initialized
    float4 D[2];
    {
        float2 bav = *(const float2*)(cst.ba + 2 * cl);
        D[0] = make_float4(bav.x, bav.y, bav.x, bav.y);
        D[1] = D[0];
    }

    // ---- chunked stage + tensor-core phase A (2 chunks of 32 channels) ----
#pragma unroll
    for (int cb = 0; cb < 64; cb += 32) {
        // stage: lane owns channels (cb+2l, cb+2l+1); rv stored tf32-rounded
        const int c0 = cb + l * 2;
        float2 s12 = *(const float2*)(cst.s1 + c0);
        float2 xq2;
        {
            float2 q2 = *(const float2*)(g_q + (size_t)i * 64 + c0);
            float2 b2v = *(const float2*)(cst.bb1 + c0);
            xq2.x = fmaf(-q2.x, s12.x, b2v.x);
            xq2.y = fmaf(-q2.y, s12.y, b2v.y);
        }
        float2 w02 = *(const float2*)(cst.ws0 + c0);
        float2 w12 = *(const float2*)(cst.ws1 + c0);
        float2 w22 = *(const float2*)(cst.ws2 + c0);
        float2 wb2 = *(const float2*)(cst.wsb + c0);

#pragma unroll 4
        for (int jj = 0; jj < 16; jj++) {
            int    nb = __shfl_sync(0xffffffffu, nj, jj, 16);        // reg -> LDG addr
            float2 kv = *(const float2*)(g_k + (size_t)nb * 64 + c0);
            float4 h4 = *(const float4*)(rvp + jj * RV_J_STRIDE + 32); // bcast LDS
            float2 pe = fma2(make_float2(h4.x, h4.x), w02,
                        fma2(make_float2(h4.y, h4.y), w12,
                        fma2(make_float2(h4.z, h4.z), w22, wb2)));
            float2 arg = fma2(kv, s12, add2(xq2, pe));
            *(float2*)(rvp + jj * RV_J_STRIDE + l * 2) =
                make_float2(to_tf32(fmaxf(arg.x, 0.f)),
                            to_tf32(fmaxf(arg.y, 0.f)));
        }
        __syncwarp();

        // phase A partial on tensor cores: D[o] += rv_chunk @ Wa[cb..cb+31]
#pragma unroll
        for (int ks = 0; ks < 4; ks++) {
            const int k0 = ks * 8;
            uint32_t b0 = __float_as_uint(cst.wa[(cb + k0 + cl) * 8 + qd]);
            uint32_t b1 = __float_as_uint(cst.wa[(cb + k0 + cl + 4) * 8 + qd]);
#pragma unroll
            for (int o = 0; o < 2; o++) {
                const float* rq = rv_s + (wpt + o) * RV_PT_STRIDE;
                uint32_t a[4];
                a[0] = __float_as_uint(rq[qd * RV_J_STRIDE + k0 + cl]);
                a[1] = __float_as_uint(rq[(qd + 8) * RV_J_STRIDE + k0 + cl]);
                a[2] = __float_as_uint(rq[qd * RV_J_STRIDE + k0 + cl + 4]);
                a[3] = __float_as_uint(rq[(qd + 8) * RV_J_STRIDE + k0 + cl + 4]);
                mma_tf32(D[o], a, b0, b1);
            }
        }
        __syncwarp();   // mma reads done before next chunk overwrites rv
    }

    // ---- BN2 + ReLU in-fragment, stash t into dead rv words 16..23 ----
    {
        float2 s2v  = *(const float2*)(cst.s2  + 2 * cl);
        float2 bb2v = *(const float2*)(cst.bb2 + 2 * cl);
#pragma unroll
        for (int o = 0; o < 2; o++) {
            float* rq = rv_s + (wpt + o) * RV_PT_STRIDE;
            float t0 = fmaxf(fmaf(D[o].x, s2v.x, bb2v.x), 0.f);
            float t1 = fmaxf(fmaf(D[o].y, s2v.y, bb2v.y), 0.f);
            float t2 = fmaxf(fmaf(D[o].z, s2v.x, bb2v.x), 0.f);
            float t3 = fmaxf(fmaf(D[o].w, s2v.y, bb2v.y), 0.f);
            *(float2*)(rq + qd * RV_J_STRIDE + 16 + 2 * cl)       = make_float2(t0, t1);
            *(float2*)(rq + (qd + 8) * RV_J_STRIDE + 16 + 2 * cl) = make_float2(t2, t3);
        }
    }
    __syncwarp();

    // restore lane=neighbor layout: lane l reads its own t row
    float2 a2[4];
    {
        float4 ta = *(const float4*)(rvp + l * RV_J_STRIDE + 16);
        float4 tb = *(const float4*)(rvp + l * RV_J_STRIDE + 20);
        a2[0] = make_float2(ta.x, ta.y);
        a2[1] = make_float2(ta.z, ta.w);
        a2[2] = make_float2(tb.x, tb.y);
        a2[3] = make_float2(tb.z, tb.w);
    }

    // ---- second MLP (8 -> 8); BN2+ReLU already applied ----
    float2 b2[4];
#pragma unroll
    for (int q = 0; q < 4; q++) b2[q] = *(const float2*)(cst.bw + q * 2);
#pragma unroll
    for (int m = 0; m < 8; m++) {
        float t = (m & 1) ? a2[m >> 1].y : a2[m >> 1].x;
        float2 tt = make_float2(t, t);
        const float2* wr = (const float2*)(cst.wbm + m * 8);
        b2[0] = fma2(tt, wr[0], b2[0]);
        b2[1] = fma2(tt, wr[1], b2[1]);
        b2[2] = fma2(tt, wr[2], b2[2]);
        b2[3] = fma2(tt, wr[3], b2[3]);
    }

    // ---- softmax over 16 neighbors (no max-sub: logits are O(0.2)) ----
    {
#pragma unroll
        for (int q = 0; q < 4; q++) {
            float2 v2 = b2[q];
            float e0 = __expf(v2.x);
            float e1 = __expf(v2.y);
            float s0 = e0, s1 = e1;
#pragma unroll
            for (int off = 8; off >= 1; off >>= 1) {
                s0 += __shfl_xor_sync(0xffffffffu, s0, off);
                s1 += __shfl_xor_sync(0xffffffffu, s1, off);
            }
            b2[q] = make_float2(__fdividef(e0, s0), __fdividef(e1, s1));
        }
    }
    // overlay softmax weights into dead rv words 12l..12l+7 (disjoint from h-pack)
    {
        float* wp = rvp + l * W_J_STRIDE;
        *(float4*)(wp)     = make_float4(b2[0].x, b2[0].y, b2[1].x, b2[1].y);
        *(float4*)(wp + 4) = make_float4(b2[2].x, b2[2].y, b2[3].x, b2[3].y);
    }
    __syncwarp();

    // ---- phase B: channel-parallel aggregation (fp16 v gather) ----
    const int c0 = l * 4;
    const int m0 = (l & 1) * 4;
    float4 rr0 = *(const float4*)(cst.r0 + c0);
    float4 rr1 = *(const float4*)(cst.r1 + c0);
    float4 rr2 = *(const float4*)(cst.r2 + c0);
    float4 rrb = *(const float4*)(cst.rb + c0);
    float2 acc01 = make_float2(0.f, 0.f), acc23 = make_float2(0.f, 0.f);
#pragma unroll 4
    for (int jj = 0; jj < 16; jj++) {
        int    nb = __shfl_sync(0xffffffffu, nj, jj, 16);          // reg -> LDG addr
        uint2  vr = *(const uint2*)(g_hv + (size_t)nb * 64 + c0);
        float2 v01f = __half22float2(*(__half2*)&vr.x);
        float2 v23f = __half22float2(*(__half2*)&vr.y);
        float4 h4 = *(const float4*)(rvp + jj * RV_J_STRIDE + 32); // bcast LDS
        float4 wv = *(const float4*)(rvp + jj * W_J_STRIDE + m0);
        float2 pe01 = fma2(make_float2(h4.x, h4.x), make_float2(rr0.x, rr0.y),
                      fma2(make_float2(h4.y, h4.y), make_float2(rr1.x, rr1.y),
                      fma2(make_float2(h4.z, h4.z), make_float2(rr2.x, rr2.y),
                           make_float2(rrb.x, rrb.y))));
        float2 pe23 = fma2(make_float2(h4.x, h4.x), make_float2(rr0.z, rr0.w),
                      fma2(make_float2(h4.y, h4.y), make_float2(rr1.z, rr1.w),
                      fma2(make_float2(h4.z, h4.z), make_float2(rr2.z, rr2.w),
                           make_float2(rrb.z, rrb.w))));
        acc01 = fma2(add2(v01f, pe01), make_float2(wv.x, wv.y), acc01);
        acc23 = fma2(add2(v23f, pe23), make_float2(wv.z, wv.w), acc23);
    }
    if (i0 < N)
        *(float4*)(outp + (size_t)i0 * 64 + c0) =
            make_float4(acc01.x, acc01.y, acc23.x, acc23.y);
}

// ============================================================================
extern "C" void kernel_launch(void* const* d_in, const int* in_sizes, int n_in,
                              void* d_out, int out_size) {
    const float* p   = (const float*)d_in[0];
    const float* x   = (const float*)d_in[1];
    const int*   idx = (const int*)d_in[2];
    const float* Wq  = (const float*)d_in[3];  const float* bq  = (const float*)d_in[4];
    const float* Wk  = (const float*)d_in[5];  const float* bk  = (const float*)d_in[6];
    const float* Wv  = (const float*)d_in[7];  const float* bv  = (const float*)d_in[8];
    const float* Wp1 = (const float*)d_in[9];  const float* bp1 = (const float*)d_in[10];
    const float* gp  = (const float*)d_in[11]; const float* bp  = (const float*)d_in[12];
    const float* Wp2 = (const float*)d_in[13]; const float* bp2 = (const float*)d_in[14];
    const float* g1  = (const float*)d_in[15]; const float* bb1 = (const float*)d_in[16];
    const float* Wa  = (const float*)d_in[17]; const float* ba  = (const float*)d_in[18];
    const float* g2  = (const float*)d_in[19]; const float* bb2 = (const float*)d_in[20];
    const float* Wb  = (const float*)d_in[21]; const float* bw  = (const float*)d_in[22];

    int N = in_sizes[0] / 3;
    if (N > MAXN) N = MAXN;  // scratch bound (problem shape is N=100000)
    int numTiles = (N + 63) / 64;

    const int qkv_dyn  = (64 * WS_STRIDE + 2 * 64 * XS_STRIDE) * (int)sizeof(float); // 86016
    const int attn_dyn = 8 * RV_PT_STRIDE * (int)sizeof(float);                      // 18688
    cudaFuncSetAttribute(qkv_kernel,  cudaFuncAttributeMaxDynamicSharedMemorySize, qkv_dyn);
    cudaFuncSetAttribute(attn_kernel, cudaFuncAttributeMaxDynamicSharedMemorySize, attn_dyn);

    qkv_kernel<<<QKV_GRID, 256, qkv_dyn>>>(x, p, Wq, Wk, Wv, bq, bk, bv, N, numTiles);

    attn_kernel<<<(N + 7) / 8, 128, attn_dyn>>>(idx, Wp1, bp1, gp, bp, Wp2, bp2,
                                                g1, bb1, Wa, ba, g2, bb2, Wb, bw,
                                                (float*)d_out, N);
}

// round 16
// speedup vs baseline: 1.9031x; 1.2326x over previous
#include <cuda_runtime.h>
#include <cuda_fp16.h>
#include <cstdint>
#include <cstddef>

#define MAXN 131072

// scratch (device globals: no allocation allowed)
__device__ float  g_q[MAXN * 64];
__device__ __half g_hk[MAXN * 64];   // k stored fp16 (1 line per row gather)
__device__ __half g_hv[MAXN * 64];   // v stored fp16
__device__ float4 g_p4[MAXN];

// ---- packed fp32x2 ops (sm_103a FFMA2 path) ----
__device__ __forceinline__ float2 fma2(float2 a, float2 b, float2 c) {
    float2 d;
    asm("fma.rn.f32x2 %0, %1, %2, %3;"
        : "=l"(*(unsigned long long*)&d)
        : "l"(*(unsigned long long*)&a),
          "l"(*(unsigned long long*)&b),
          "l"(*(unsigned long long*)&c));
    return d;
}
__device__ __forceinline__ float2 add2(float2 a, float2 b) {
    float2 d;
    asm("add.rn.f32x2 %0, %1, %2;"
        : "=l"(*(unsigned long long*)&d)
        : "l"(*(unsigned long long*)&a),
          "l"(*(unsigned long long*)&b));
    return d;
}

// ---- tf32 / mma helpers ----
__device__ __forceinline__ float to_tf32(float f) {
    uint32_t u;
    asm("cvt.rna.tf32.f32 %0, %1;" : "=r"(u) : "f"(f));
    return __uint_as_float(u);
}
__device__ __forceinline__ void mma_tf32(float4& d, const uint32_t* a,
                                         uint32_t b0, uint32_t b1) {
    asm volatile(
        "mma.sync.aligned.m16n8k8.row.col.f32.tf32.tf32.f32 "
        "{%0,%1,%2,%3}, {%4,%5,%6,%7}, {%8,%9}, {%0,%1,%2,%3};"
        : "+f"(d.x), "+f"(d.y), "+f"(d.z), "+f"(d.w)
        : "r"(a[0]), "r"(a[1]), "r"(a[2]), "r"(a[3]), "r"(b0), "r"(b1));
}
__device__ __forceinline__ void mma_f16(float4& d, uint32_t a0, uint32_t a1,
                                        uint32_t a2, uint32_t a3,
                                        uint32_t b0, uint32_t b1) {
    asm volatile(
        "mma.sync.aligned.m16n8k16.row.col.f32.f16.f16.f32 "
        "{%0,%1,%2,%3}, {%4,%5,%6,%7}, {%8,%9}, {%0,%1,%2,%3};"
        : "+f"(d.x), "+f"(d.y), "+f"(d.z), "+f"(d.w)
        : "r"(a0), "r"(a1), "r"(a2), "r"(a3), "r"(b0), "r"(b1));
}
__device__ __forceinline__ void cp_async16(void* smem_dst, const void* gmem_src) {
    uint32_t s = (uint32_t)__cvta_generic_to_shared(smem_dst);
    asm volatile("cp.async.cg.shared.global [%0], [%1], 16;"
                 :: "r"(s), "l"(gmem_src) : "memory");
}
__device__ __forceinline__ void cp_commit() {
    asm volatile("cp.async.commit_group;" ::: "memory");
}
__device__ __forceinline__ void cp_wait0() {
    asm volatile("cp.async.wait_group 0;" ::: "memory");
}

// ============================================================================
// Kernel 1: PERSISTENT fused q/k/v via tf32 HMMA + p -> g_p4 repack.
// k and v outputs converted to fp16 in the epilogue (halves attn gather lines).
// ============================================================================
#define XS_STRIDE 68
#define WS_STRIDE 200
#define QKV_GRID 304

__global__ __launch_bounds__(256, 2) void qkv_kernel(
    const float* __restrict__ x, const float* __restrict__ p,
    const float* __restrict__ Wq, const float* __restrict__ Wk,
    const float* __restrict__ Wv,
    const float* __restrict__ bq, const float* __restrict__ bk,
    const float* __restrict__ bv, int N, int numTiles)
{
    extern __shared__ float smem[];
    float* ws   = smem;                          // 64*200 = 51200B
    float* buf0 = smem + 64 * WS_STRIDE;         // 64*68  = 17408B
    float* buf1 = buf0 + 64 * XS_STRIDE;         // 64*68  = 17408B
    const int tid = threadIdx.x;

    // ---- weights once per block (cvt to tf32 here) ----
    {
        const float* Wm[3] = {Wq, Wk, Wv};
#pragma unroll
        for (int m = 0; m < 3; m++) {
            const float4* src = (const float4*)Wm[m];
            for (int e = tid; e < 1024; e += 256) {
                int k = e >> 4, c4 = e & 15;
                float4 v = src[e];
                v.x = to_tf32(v.x); v.y = to_tf32(v.y);
                v.z = to_tf32(v.z); v.w = to_tf32(v.w);
                *(float4*)(ws + k * WS_STRIDE + m * 64 + c4 * 4) = v;
            }
        }
    }

    const int lane  = tid & 31;
    const int warp  = tid >> 5;
    const int rbase = (warp & 1) * 32;
    const int cwb   = (warp >> 1) * 48;
    const int qd    = lane >> 2;
    const int cl    = lane & 3;

    const float* bias[3] = {bq, bk, bv};
    float bfr[6][2];
#pragma unroll
    for (int t6 = 0; t6 < 6; t6++) {
        int g = cwb + t6 * 8 + 2 * cl;
        bfr[t6][0] = bias[g >> 6][g & 63];
        bfr[t6][1] = bias[g >> 6][(g & 63) + 1];
    }

    float* bufs[2] = {buf0, buf1};

    // ---- prologue: prefetch first tile ----
    int t0 = blockIdx.x;
    if (t0 < numTiles) {
        int rowBase = t0 * 64;
        for (int e = tid; e < 1024; e += 256) {
            int r = e >> 4, c4 = e & 15;
            float* d = buf0 + r * XS_STRIDE + c4 * 4;
            int row = rowBase + r;
            if (row < N)
                cp_async16(d, x + (size_t)row * 64 + c4 * 4);
            else
                *(float4*)d = make_float4(0.f, 0.f, 0.f, 0.f);
        }
    }
    cp_commit();

    int cur = 0;
    for (int t = blockIdx.x; t < numTiles; t += QKV_GRID) {
        const int rowBase = t * 64;
        cp_wait0();
        __syncthreads();

        // prefetch next tile into the other buffer
        {
            int tn = t + QKV_GRID;
            if (tn < numTiles) {
                int rb2 = tn * 64;
                float* dst = bufs[cur ^ 1];
                for (int e = tid; e < 1024; e += 256) {
                    int r = e >> 4, c4 = e & 15;
                    float* d = dst + r * XS_STRIDE + c4 * 4;
                    int row = rb2 + r;
                    if (row < N)
                        cp_async16(d, x + (size_t)row * 64 + c4 * 4);
                    else
                        *(float4*)d = make_float4(0.f, 0.f, 0.f, 0.f);
                }
            }
            cp_commit();
        }
        // p repack for this tile
        if (tid < 64) {
            int row = rowBase + tid;
            if (row < N)
                g_p4[row] = make_float4(p[row * 3], p[row * 3 + 1],
                                        p[row * 3 + 2], 0.f);
        }

        float* xs = bufs[cur];

        // ---- mainloop ----
        float4 C[2][6];
#pragma unroll
        for (int rt = 0; rt < 2; rt++)
#pragma unroll
            for (int t6 = 0; t6 < 6; t6++)
                C[rt][t6] = make_float4(bfr[t6][0], bfr[t6][1],
                                        bfr[t6][0], bfr[t6][1]);

#pragma unroll
        for (int ks = 0; ks < 8; ks++) {
            const int k0 = ks * 8;
            uint32_t a[2][4];
#pragma unroll
            for (int rt = 0; rt < 2; rt++) {
                int r = rbase + rt * 16 + qd;
                a[rt][0] = __float_as_uint(xs[r * XS_STRIDE + k0 + cl]);
                a[rt][1] = __float_as_uint(xs[(r + 8) * XS_STRIDE + k0 + cl]);
                a[rt][2] = __float_as_uint(xs[r * XS_STRIDE + k0 + cl + 4]);
                a[rt][3] = __float_as_uint(xs[(r + 8) * XS_STRIDE + k0 + cl + 4]);
            }
#pragma unroll
            for (int t6 = 0; t6 < 6; t6++) {
                int n0 = cwb + t6 * 8;
                uint32_t b0 = __float_as_uint(ws[(k0 + cl) * WS_STRIDE + n0 + qd]);
                uint32_t b1 = __float_as_uint(ws[(k0 + cl + 4) * WS_STRIDE + n0 + qd]);
                mma_tf32(C[0][t6], a[0], b0, b1);
                mma_tf32(C[1][t6], a[1], b0, b1);
            }
        }
        __syncthreads();          // xs dead -> reuse as staging

        // ---- epilogue: q fp32; k,v fp16 ----
        float* stg = xs;
#pragma unroll
        for (int m = 0; m < 3; m++) {
#pragma unroll
            for (int t6 = 0; t6 < 6; t6++) {
                if (((cwb + 8 * t6) >> 6) == m) {
                    int cc = (cwb + 8 * t6 + 2 * cl) & 63;
#pragma unroll
                    for (int rt = 0; rt < 2; rt++) {
                        int lr0 = rbase + rt * 16 + qd;
                        *(float2*)(stg + lr0 * XS_STRIDE + cc) =
                            make_float2(C[rt][t6].x, C[rt][t6].y);
                        *(float2*)(stg + (lr0 + 8) * XS_STRIDE + cc) =
                            make_float2(C[rt][t6].z, C[rt][t6].w);
                    }
                }
            }
            __syncthreads();
            if (m == 0) {
                for (int e = tid; e < 1024; e += 256) {
                    int r = e >> 4, c4 = e & 15;
                    int row = rowBase + r;
                    if (row < N)
                        *(float4*)(g_q + (size_t)row * 64 + c4 * 4) =
                            *(const float4*)(stg + r * XS_STRIDE + c4 * 4);
                }
            } else {
                __half* outh = (m == 1) ? g_hk : g_hv;
                for (int e = tid; e < 1024; e += 256) {
                    int r = e >> 4, c4 = e & 15;
                    int row = rowBase + r;
                    if (row < N) {
                        float4 vv = *(const float4*)(stg + r * XS_STRIDE + c4 * 4);
                        __half2 h2[2];
                        h2[0] = __floats2half2_rn(vv.x, vv.y);
                        h2[1] = __floats2half2_rn(vv.z, vv.w);
                        *(uint2*)(outh + (size_t)row * 64 + c4 * 4) = *(uint2*)h2;
                    }
                }
            }
            __syncthreads();
        }
        cur ^= 1;
    }
}

// ============================================================================
// Kernel 2: fused attention. Single-pass stage: k gathered fp16 (full 64-ch
// row = 1 line/pt), rv stored fp16 (64 halves in the same 128B row footprint
// as the old 32 floats — smem layout, h-pack (words 32..35), stash (16..23)
// and softmax overlay (12l..) offsets unchanged). Phase A = 4x
// mma.m16n8k16.f16: A frags are aligned half2 LDS.32 (banks 4qd+cl,
// conflict-free); Wa pre-packed into exact B-frag uint32 pairs.
// ============================================================================
struct __align__(16) K2C {
    float s1[64], bb1[64];
    float ws0[64], ws1[64], ws2[64], wsb[64];  // s1-scaled Wp2 rows + s1*bp2
    float r0[64], r1[64], r2[64], rb[64];      // raw Wp2 rows + bp2 (phase B)
    uint32_t wab0[128], wab1[128];             // Wa packed fp16 B-frags [ks][lane]
    float wbm[64];                             // Wb [8][8]
    float s2[8], bb2[8], ba[8], bw[8];
    float wp1[9], bp1v[3], spv[3], bpv[3];
};

#define RV_J_STRIDE 36          // 36 float words/row: 64 halves rv + h-pack pad
#define RV_PT_STRIDE 584        // 16*36 + 8 stagger; % 32 == 8
#define W_J_STRIDE 12           // softmax weight row (8 + 4 gap), 48B

__global__ __launch_bounds__(128, 8) void attn_kernel(
    const int* __restrict__ idx,
    const float* __restrict__ Wp1, const float* __restrict__ bp1,
    const float* __restrict__ gp,  const float* __restrict__ bp,
    const float* __restrict__ Wp2, const float* __restrict__ bp2,
    const float* __restrict__ g1,  const float* __restrict__ bb1,
    const float* __restrict__ Wa,  const float* __restrict__ ba,
    const float* __restrict__ g2,  const float* __restrict__ bb2,
    const float* __restrict__ Wb,  const float* __restrict__ bw,
    float* __restrict__ outp, int N)
{
    __shared__ K2C cst;
    extern __shared__ __align__(16) float rv_s[];  // 8 * RV_PT_STRIDE floats

    const int tid = threadIdx.x;
    const float RSQ = rsqrtf(1.f + 1e-5f);

    // ---- constant prep ----
    if (tid < 64) {
        float s1v = g1[tid] * RSQ;
        cst.s1[tid]  = s1v;
        cst.bb1[tid] = bb1[tid];
        float w0 = Wp2[tid], w1 = Wp2[64 + tid], w2 = Wp2[128 + tid], bb = bp2[tid];
        cst.r0[tid] = w0;        cst.r1[tid] = w1;
        cst.r2[tid] = w2;        cst.rb[tid] = bb;
        cst.ws0[tid] = w0 * s1v; cst.ws1[tid] = w1 * s1v;
        cst.ws2[tid] = w2 * s1v; cst.wsb[tid] = bb * s1v;
        cst.wbm[tid] = Wb[tid];
    }
    // Wa packed into fp16 B fragments: b0 rows (16ks+2cl, +1), b1 rows (+8,+9), col qd
    for (int e = tid; e < 256; e += 128) {
        int b  = e >> 7, id = e & 127;
        int ks = id >> 5, ln = id & 31;
        int q_ = ln >> 2, c_ = ln & 3;
        int r  = 16 * ks + 2 * c_ + 8 * b;
        __half2 hp = __floats2half2_rn(Wa[r * 8 + q_], Wa[(r + 1) * 8 + q_]);
        uint32_t uv = *(uint32_t*)&hp;
        if (b) cst.wab1[ks * 32 + ln] = uv; else cst.wab0[ks * 32 + ln] = uv;
    }
    if (tid < 8) {
        cst.s2[tid] = g2[tid] * RSQ;
        cst.bb2[tid] = bb2[tid];
        cst.ba[tid]  = ba[tid];
        cst.bw[tid]  = bw[tid];
    }
    if (tid >= 64 && tid < 73) cst.wp1[tid - 64] = Wp1[tid - 64];
    if (tid >= 80 && tid < 83) {
        int t = tid - 80;
        cst.bp1v[t] = bp1[t]; cst.spv[t] = gp[t] * RSQ; cst.bpv[t] = bp[t];
    }
    __syncthreads();

    const int pt   = tid >> 4;
    const int l    = tid & 15;
    const int lane = tid & 31;
    const int qd   = lane >> 2;
    const int cl   = lane & 3;
    const int wpt  = (tid >> 5) * 2;
    const int i0 = blockIdx.x * 8 + pt;
    const int i  = (i0 < N) ? i0 : 0;

    float* rvp = rv_s + pt * RV_PT_STRIDE;

    // ---- prep (lane = neighbor l): nj in register + pe hidden -> pad ----
    const int nj = idx[i * 16 + l];
    {
        float4 pc = g_p4[i];
        float4 pn = g_p4[nj];
        float prx = pn.x - pc.x, pry = pn.y - pc.y, prz = pn.z - pc.z;
        float u0 = cst.bp1v[0] + prx * cst.wp1[0] + pry * cst.wp1[3] + prz * cst.wp1[6];
        float u1 = cst.bp1v[1] + prx * cst.wp1[1] + pry * cst.wp1[4] + prz * cst.wp1[7];
        float u2 = cst.bp1v[2] + prx * cst.wp1[2] + pry * cst.wp1[5] + prz * cst.wp1[8];
        float h0 = fmaxf(fmaf(u0, cst.spv[0], cst.bpv[0]), 0.f);
        float h1 = fmaxf(fmaf(u1, cst.spv[1], cst.bpv[1]), 0.f);
        float h2 = fmaxf(fmaf(u2, cst.spv[2], cst.bpv[2]), 0.f);
        *(float4*)(rvp + l * RV_J_STRIDE + 32) = make_float4(h0, h1, h2, 0.f);
    }
    __syncwarp();

    // mma accumulators (one 16x8 per point), bias-initialized
    float4 D[2];
    {
        float2 bav = *(const float2*)(cst.ba + 2 * cl);
        D[0] = make_float4(bav.x, bav.y, bav.x, bav.y);
        D[1] = D[0];
    }

    // ---- single-pass stage: lane owns channels 4l..4l+3 ----
    {
        const int c0 = l * 4;
        float4 s14 = *(const float4*)(cst.s1 + c0);
        float4 xq4;
        {
            float4 q4 = *(const float4*)(g_q + (size_t)i * 64 + c0);
            float4 b4 = *(const float4*)(cst.bb1 + c0);
            xq4.x = fmaf(-q4.x, s14.x, b4.x);
            xq4.y = fmaf(-q4.y, s14.y, b4.y);
            xq4.z = fmaf(-q4.z, s14.z, b4.z);
            xq4.w = fmaf(-q4.w, s14.w, b4.w);
        }
        float4 w04 = *(const float4*)(cst.ws0 + c0);
        float4 w14 = *(const float4*)(cst.ws1 + c0);
        float4 w24 = *(const float4*)(cst.ws2 + c0);
        float4 wb4 = *(const float4*)(cst.wsb + c0);

#pragma unroll 4
        for (int jj = 0; jj < 16; jj++) {
            int   nb = __shfl_sync(0xffffffffu, nj, jj, 16);        // reg -> LDG addr
            uint2 kv2 = *(const uint2*)(g_hk + (size_t)nb * 64 + c0);
            float4 h4 = *(const float4*)(rvp + jj * RV_J_STRIDE + 32); // bcast LDS
            float2 kf01 = __half22float2(*(__half2*)&kv2.x);
            float2 kf23 = __half22float2(*(__half2*)&kv2.y);
            float2 pe01 = fma2(make_float2(h4.x, h4.x), make_float2(w04.x, w04.y),
                          fma2(make_float2(h4.y, h4.y), make_float2(w14.x, w14.y),
                          fma2(make_float2(h4.z, h4.z), make_float2(w24.x, w24.y),
                               make_float2(wb4.x, wb4.y))));
            float2 pe23 = fma2(make_float2(h4.x, h4.x), make_float2(w04.z, w04.w),
                          fma2(make_float2(h4.y, h4.y), make_float2(w14.z, w14.w),
                          fma2(make_float2(h4.z, h4.z), make_float2(w24.z, w24.w),
                               make_float2(wb4.z, wb4.w))));
            float2 a01 = fma2(kf01, make_float2(s14.x, s14.y),
                              add2(make_float2(xq4.x, xq4.y), pe01));
            float2 a23 = fma2(kf23, make_float2(s14.z, s14.w),
                              add2(make_float2(xq4.z, xq4.w), pe23));
            __half2 ha = __floats2half2_rn(fmaxf(a01.x, 0.f), fmaxf(a01.y, 0.f));
            __half2 hb = __floats2half2_rn(fmaxf(a23.x, 0.f), fmaxf(a23.y, 0.f));
            uint2 st;
            st.x = *(uint32_t*)&ha;
            st.y = *(uint32_t*)&hb;
            *(uint2*)(rvp + jj * RV_J_STRIDE + 2 * l) = st;  // halves 4l..4l+3
        }
    }
    __syncwarp();

    // ---- phase A: 4x m16n8k16 fp16 mma ----
#pragma unroll
    for (int ks = 0; ks < 4; ks++) {
        uint32_t b0 = cst.wab0[ks * 32 + lane];
        uint32_t b1 = cst.wab1[ks * 32 + lane];
#pragma unroll
        for (int o = 0; o < 2; o++) {
            const uint32_t* rq = (const uint32_t*)(rv_s + (wpt + o) * RV_PT_STRIDE);
            uint32_t a0 = rq[qd * RV_J_STRIDE + 8 * ks + cl];
            uint32_t a1 = rq[(qd + 8) * RV_J_STRIDE + 8 * ks + cl];
            uint32_t a2 = rq[qd * RV_J_STRIDE + 8 * ks + cl + 4];
            uint32_t a3 = rq[(qd + 8) * RV_J_STRIDE + 8 * ks + cl + 4];
            mma_f16(D[o], a0, a1, a2, a3, b0, b1);
        }
    }
    __syncwarp();   // mma reads done before stash overwrites rv words

    // ---- BN2 + ReLU in-fragment, stash t into dead rv words 16..23 ----
    {
        float2 s2v  = *(const float2*)(cst.s2  + 2 * cl);
        float2 bb2v = *(const float2*)(cst.bb2 + 2 * cl);
#pragma unroll
        for (int o = 0; o < 2; o++) {
            float* rq = rv_s + (wpt + o) * RV_PT_STRIDE;
            float t0 = fmaxf(fmaf(D[o].x, s2v.x, bb2v.x), 0.f);
            float t1 = fmaxf(fmaf(D[o].y, s2v.y, bb2v.y), 0.f);
            float t2 = fmaxf(fmaf(D[o].z, s2v.x, bb2v.x), 0.f);
            float t3 = fmaxf(fmaf(D[o].w, s2v.y, bb2v.y), 0.f);
            *(float2*)(rq + qd * RV_J_STRIDE + 16 + 2 * cl)       = make_float2(t0, t1);
            *(float2*)(rq + (qd + 8) * RV_J_STRIDE + 16 + 2 * cl) = make_float2(t2, t3);
        }
    }
    __syncwarp();

    // restore lane=neighbor layout: lane l reads its own t row
    float2 a2[4];
    {
        float4 ta = *(const float4*)(rvp + l * RV_J_STRIDE + 16);
        float4 tb = *(const float4*)(rvp + l * RV_J_STRIDE + 20);
        a2[0] = make_float2(ta.x, ta.y);
        a2[1] = make_float2(ta.z, ta.w);
        a2[2] = make_float2(tb.x, tb.y);
        a2[3] = make_float2(tb.z, tb.w);
    }

    // ---- second MLP (8 -> 8); BN2+ReLU already applied ----
    float2 b2[4];
#pragma unroll
    for (int q = 0; q < 4; q++) b2[q] = *(const float2*)(cst.bw + q * 2);
#pragma unroll
    for (int m = 0; m < 8; m++) {
        float t = (m & 1) ? a2[m >> 1].y : a2[m >> 1].x;
        float2 tt = make_float2(t, t);
        const float2* wr = (const float2*)(cst.wbm + m * 8);
        b2[0] = fma2(tt, wr[0], b2[0]);
        b2[1] = fma2(tt, wr[1], b2[1]);
        b2[2] = fma2(tt, wr[2], b2[2]);
        b2[3] = fma2(tt, wr[3], b2[3]);
    }

    // ---- softmax over 16 neighbors (no max-sub: logits are O(0.2)) ----
    {
#pragma unroll
        for (int q = 0; q < 4; q++) {
            float2 v2 = b2[q];
            float e0 = __expf(v2.x);
            float e1 = __expf(v2.y);
            float s0 = e0, s1 = e1;
#pragma unroll
            for (int off = 8; off >= 1; off >>= 1) {
                s0 += __shfl_xor_sync(0xffffffffu, s0, off);
                s1 += __shfl_xor_sync(0xffffffffu, s1, off);
            }
            b2[q] = make_float2(__fdividef(e0, s0), __fdividef(e1, s1));
        }
    }
    // overlay softmax weights into dead rv words 12l..12l+7 (disjoint from h-pack)
    {
        float* wp = rvp + l * W_J_STRIDE;
        *(float4*)(wp)     = make_float4(b2[0].x, b2[0].y, b2[1].x, b2[1].y);
        *(float4*)(wp + 4) = make_float4(b2[2].x, b2[2].y, b2[3].x, b2[3].y);
    }
    __syncwarp();

    // ---- phase B: channel-parallel aggregation (fp16 v gather) ----
    const int c0 = l * 4;
    const int m0 = (l & 1) * 4;
    float4 rr0 = *(const float4*)(cst.r0 + c0);
    float4 rr1 = *(const float4*)(cst.r1 + c0);
    float4 rr2 = *(const float4*)(cst.r2 + c0);
    float4 rrb = *(const float4*)(cst.rb + c0);
    float2 acc01 = make_float2(0.f, 0.f), acc23 = make_float2(0.f, 0.f);
#pragma unroll 4
    for (int jj = 0; jj < 16; jj++) {
        int    nb = __shfl_sync(0xffffffffu, nj, jj, 16);
        uint2  vr = *(const uint2*)(g_hv + (size_t)nb * 64 + c0);
        float2 v01f = __half22float2(*(__half2*)&vr.x);
        float2 v23f = __half22float2(*(__half2*)&vr.y);
        float4 h4 = *(const float4*)(rvp + jj * RV_J_STRIDE + 32);
        float4 wv = *(const float4*)(rvp + jj * W_J_STRIDE + m0);
        float2 pe01 = fma2(make_float2(h4.x, h4.x), make_float2(rr0.x, rr0.y),
                      fma2(make_float2(h4.y, h4.y), make_float2(rr1.x, rr1.y),
                      fma2(make_float2(h4.z, h4.z), make_float2(rr2.x, rr2.y),
                           make_float2(rrb.x, rrb.y))));
        float2 pe23 = fma2(make_float2(h4.x, h4.x), make_float2(rr0.z, rr0.w),
                      fma2(make_float2(h4.y, h4.y), make_float2(rr1.z, rr1.w),
                      fma2(make_float2(h4.z, h4.z), make_float2(rr2.z, rr2.w),
                           make_float2(rrb.z, rrb.w))));
        acc01 = fma2(add2(v01f, pe01), make_float2(wv.x, wv.y), acc01);
        acc23 = fma2(add2(v23f, pe23), make_float2(wv.z, wv.w), acc23);
    }
    if (i0 < N)
        *(float4*)(outp + (size_t)i0 * 64 + c0) =
            make_float4(acc01.x, acc01.y, acc23.x, acc23.y);
}

// ============================================================================
extern "C" void kernel_launch(void* const* d_in, const int* in_sizes, int n_in,
                              void* d_out, int out_size) {
    const float* p   = (const float*)d_in[0];
    const float* x   = (const float*)d_in[1];
    const int*   idx = (const int*)d_in[2];
    const float* Wq  = (const float*)d_in[3];  const float* bq  = (const float*)d_in[4];
    const float* Wk  = (const float*)d_in[5];  const float* bk  = (const float*)d_in[6];
    const float* Wv  = (const float*)d_in[7];  const float* bv  = (const float*)d_in[8];
    const float* Wp1 = (const float*)d_in[9];  const float* bp1 = (const float*)d_in[10];
    const float* gp  = (const float*)d_in[11]; const float* bp  = (const float*)d_in[12];
    const float* Wp2 = (const float*)d_in[13]; const float* bp2 = (const float*)d_in[14];
    const float* g1  = (const float*)d_in[15]; const float* bb1 = (const float*)d_in[16];
    const float* Wa  = (const float*)d_in[17]; const float* ba  = (const float*)d_in[18];
    const float* g2  = (const float*)d_in[19]; const float* bb2 = (const float*)d_in[20];
    const float* Wb  = (const float*)d_in[21]; const float* bw  = (const float*)d_in[22];

    int N = in_sizes[0] / 3;
    if (N > MAXN) N = MAXN;  // scratch bound (problem shape is N=100000)
    int numTiles = (N + 63) / 64;

    const int qkv_dyn  = (64 * WS_STRIDE + 2 * 64 * XS_STRIDE) * (int)sizeof(float); // 86016
    const int attn_dyn = 8 * RV_PT_STRIDE * (int)sizeof(float);                      // 18688
    cudaFuncSetAttribute(qkv_kernel,  cudaFuncAttributeMaxDynamicSharedMemorySize, qkv_dyn);
    cudaFuncSetAttribute(attn_kernel, cudaFuncAttributeMaxDynamicSharedMemorySize, attn_dyn);

    qkv_kernel<<<QKV_GRID, 256, qkv_dyn>>>(x, p, Wq, Wk, Wv, bq, bk, bv, N, numTiles);

    attn_kernel<<<(N + 7) / 8, 128, attn_dyn>>>(idx, Wp1, bp1, gp, bp, Wp2, bp2,
                                                g1, bb1, Wa, ba, g2, bb2, Wb, bw,
                                                (float*)d_out, N);
}